// round 1
// baseline (speedup 1.0000x reference)
#include <cuda_runtime.h>

#define BB   2
#define SS   2048
#define HH   16
#define DK   64
#define DM   1024
#define MTOT (BB*SS)   // 4096

// Scratch for head-major Q/K/V: [B,H,S,Dk] = 2*16*2048*64 floats = 16 MB each
__device__ float g_q[BB*HH*SS*DK];
__device__ float g_k[BB*HH*SS*DK];
__device__ float g_v[BB*HH*SS*DK];

// ---------------------------------------------------------------------------
// QKV projection GEMM: C[m,n] = sum_k x[m,k]*W[k,n] + bias[n]
// Output scattered into head-major [B,H,S,Dk] (n = h*64 + d).
// Tile 64x64, K-step 16, 256 threads, 4x4 micro-tile per thread.
// ---------------------------------------------------------------------------
__global__ __launch_bounds__(256) void qkv_gemm_kernel(
    const float* __restrict__ x, const float* __restrict__ W,
    const float* __restrict__ bias, int sel)
{
    __shared__ float As[16][64];   // [k][m]
    __shared__ float Bs[16][64];   // [k][n]

    float* out = (sel == 0) ? g_q : (sel == 1) ? g_k : g_v;

    const int t  = threadIdx.x;
    const int tx = t & 15;
    const int ty = t >> 4;
    const int m0 = blockIdx.y * 64;
    const int n0 = blockIdx.x * 64;

    const int arow = t >> 2;           // 0..63
    const int acg  = (t & 3) * 4;      // 0,4,8,12
    const int brow = t >> 4;           // 0..15
    const int bcg  = (t & 15) * 4;     // 0..60

    const float* xp = x + (size_t)(m0 + arow) * DM + acg;
    const float* wp = W + (size_t)brow * DM + n0 + bcg;

    float acc[4][4] = {};

    for (int k0 = 0; k0 < DM; k0 += 16) {
        float4 av = *(const float4*)(xp + k0);
        float4 bv = *(const float4*)(wp + (size_t)k0 * DM);
        As[acg + 0][arow] = av.x;
        As[acg + 1][arow] = av.y;
        As[acg + 2][arow] = av.z;
        As[acg + 3][arow] = av.w;
        *(float4*)&Bs[brow][bcg] = bv;
        __syncthreads();

        #pragma unroll
        for (int kk = 0; kk < 16; kk++) {
            float4 a = *(const float4*)&As[kk][ty * 4];
            float4 b = *(const float4*)&Bs[kk][tx * 4];
            float aa[4] = {a.x, a.y, a.z, a.w};
            float bb[4] = {b.x, b.y, b.z, b.w};
            #pragma unroll
            for (int i = 0; i < 4; i++)
                #pragma unroll
                for (int j = 0; j < 4; j++)
                    acc[i][j] += aa[i] * bb[j];
        }
        __syncthreads();
    }

    // Epilogue: add bias, scatter to [B,H,S,Dk]
    const int h = n0 / DK;             // one head per 64-wide tile
    float4 bv = *(const float4*)(bias + n0 + tx * 4);
    #pragma unroll
    for (int i = 0; i < 4; i++) {
        int m  = m0 + ty * 4 + i;
        int b_ = m / SS;
        int s  = m % SS;
        float4 r;
        r.x = acc[i][0] + bv.x;
        r.y = acc[i][1] + bv.y;
        r.z = acc[i][2] + bv.z;
        r.w = acc[i][3] + bv.w;
        *(float4*)(out + (((size_t)(b_ * HH + h) * SS + s) * DK) + tx * 4) = r;
    }
}

// ---------------------------------------------------------------------------
// Flash-style attention (no max-subtraction needed: raw exp softmax).
// One block = one (b,h) pair x one 64-query tile. Streams 64-key tiles.
//   S  = (Q*0.125) K^T            (Q,K stored d-major in smem -> no conflicts)
//   P  = exp(S)  (stored transposed [k][q], ld=68)
//   ctx += P V ; den += rowsum(P) (accumulated in tx==0 lanes)
// ---------------------------------------------------------------------------
#define BQ    64
#define BKT   64
#define PS_LD 68
#define ATTN_SMEM_BYTES ((3*64*64 + 64*PS_LD + 64) * 4)   // 66816 B

__global__ __launch_bounds__(256) void attn_kernel(float* __restrict__ out)
{
    extern __shared__ float sm[];
    float* Qs   = sm;                  // [d][q]  64x64
    float* Ks   = Qs + 64 * 64;        // [d][k]  64x64
    float* Vs   = Ks + 64 * 64;        // [k][d]  64x64
    float* Ps   = Vs + 64 * 64;        // [k][q]  64x68
    float* dsum = Ps + 64 * PS_LD;     // [64]

    const int t  = threadIdx.x;
    const int tx = t & 15;
    const int ty = t >> 4;
    const int bh = blockIdx.y;         // 0..31
    const int q0 = blockIdx.x * BQ;

    const float* Qp = g_q + ((size_t)bh * SS + q0) * DK;
    const float* Kp = g_k + (size_t)bh * SS * DK;
    const float* Vp = g_v + (size_t)bh * SS * DK;

    // Load Q tile transposed ([d][q]) with 1/sqrt(Dk) folded in
    #pragma unroll
    for (int r = 0; r < 4; r++) {
        int row = (t >> 4) + r * 16;       // 0..63 (query index)
        int dg  = (t & 15) * 4;            // d group
        float4 v = *(const float4*)(Qp + (size_t)row * DK + dg);
        Qs[(dg + 0) * 64 + row] = v.x * 0.125f;
        Qs[(dg + 1) * 64 + row] = v.y * 0.125f;
        Qs[(dg + 2) * 64 + row] = v.z * 0.125f;
        Qs[(dg + 3) * 64 + row] = v.w * 0.125f;
    }

    float creg[4][4] = {};
    float dreg[4]    = {0.f, 0.f, 0.f, 0.f};

    for (int kt = 0; kt < SS / BKT; kt++) {
        const float* kp = Kp + (size_t)kt * BKT * DK;
        const float* vp = Vp + (size_t)kt * BKT * DK;

        __syncthreads();   // previous iter's Ks/Vs/Ps reads done
        #pragma unroll
        for (int r = 0; r < 4; r++) {
            int row = (t >> 4) + r * 16;
            int dg  = (t & 15) * 4;
            float4 kv = *(const float4*)(kp + (size_t)row * DK + dg);
            Ks[(dg + 0) * 64 + row] = kv.x;
            Ks[(dg + 1) * 64 + row] = kv.y;
            Ks[(dg + 2) * 64 + row] = kv.z;
            Ks[(dg + 3) * 64 + row] = kv.w;
            float4 vv = *(const float4*)(vp + (size_t)row * DK + dg);
            *(float4*)&Vs[row * 64 + dg] = vv;
        }
        __syncthreads();

        // ---- S = Q K^T (scaled) ----
        float sreg[4][4] = {};
        #pragma unroll 8
        for (int d = 0; d < 64; d++) {
            float4 a = *(const float4*)&Qs[d * 64 + ty * 4];
            float4 b = *(const float4*)&Ks[d * 64 + tx * 4];
            float aa[4] = {a.x, a.y, a.z, a.w};
            float bb[4] = {b.x, b.y, b.z, b.w};
            #pragma unroll
            for (int i = 0; i < 4; i++)
                #pragma unroll
                for (int j = 0; j < 4; j++)
                    sreg[i][j] += aa[i] * bb[j];
        }

        // ---- P = exp(S), stored transposed [k][q] ----
        #pragma unroll
        for (int j = 0; j < 4; j++)
            #pragma unroll
            for (int i = 0; i < 4; i++)
                Ps[(tx * 4 + j) * PS_LD + ty * 4 + i] = __expf(sreg[i][j]);
        __syncthreads();

        // ---- ctx += P V ; denominator in tx==0 lanes ----
        #pragma unroll 8
        for (int k = 0; k < 64; k++) {
            float4 a = *(const float4*)&Ps[k * PS_LD + ty * 4];
            float4 b = *(const float4*)&Vs[k * 64 + tx * 4];
            float aa[4] = {a.x, a.y, a.z, a.w};
            float bb[4] = {b.x, b.y, b.z, b.w};
            #pragma unroll
            for (int i = 0; i < 4; i++)
                #pragma unroll
                for (int j = 0; j < 4; j++)
                    creg[i][j] += aa[i] * bb[j];
            if (tx == 0) {
                dreg[0] += aa[0];
                dreg[1] += aa[1];
                dreg[2] += aa[2];
                dreg[3] += aa[3];
            }
        }
    }

    if (tx == 0) {
        #pragma unroll
        for (int i = 0; i < 4; i++) dsum[ty * 4 + i] = dreg[i];
    }
    __syncthreads();

    // out[b][s][h*64 + d]
    const int b_ = bh / HH;
    const int h  = bh % HH;
    #pragma unroll
    for (int i = 0; i < 4; i++) {
        float inv = 1.f / (dsum[ty * 4 + i] + 1e-8f);
        float4 r;
        r.x = creg[i][0] * inv;
        r.y = creg[i][1] * inv;
        r.z = creg[i][2] * inv;
        r.w = creg[i][3] * inv;
        size_t off = ((size_t)(b_ * SS + q0 + ty * 4 + i)) * DM + h * DK + tx * 4;
        *(float4*)(out + off) = r;
    }
}

// ---------------------------------------------------------------------------
extern "C" void kernel_launch(void* const* d_in, const int* in_sizes, int n_in,
                              void* d_out, int out_size)
{
    const float* x  = (const float*)d_in[0];
    const float* Wq = (const float*)d_in[1];
    const float* bq = (const float*)d_in[2];
    const float* Wk = (const float*)d_in[3];
    const float* bk = (const float*)d_in[4];
    const float* Wv = (const float*)d_in[5];
    const float* bv = (const float*)d_in[6];
    float* out = (float*)d_out;

    cudaFuncSetAttribute(attn_kernel,
                         cudaFuncAttributeMaxDynamicSharedMemorySize,
                         ATTN_SMEM_BYTES);

    dim3 ggrid(DM / 64, MTOT / 64);   // (16, 64)
    qkv_gemm_kernel<<<ggrid, 256>>>(x, Wq, bq, 0);
    qkv_gemm_kernel<<<ggrid, 256>>>(x, Wk, bk, 1);
    qkv_gemm_kernel<<<ggrid, 256>>>(x, Wv, bv, 2);

    dim3 agrid(SS / BQ, BB * HH);     // (32, 32)
    attn_kernel<<<agrid, 256, ATTN_SMEM_BYTES>>>(out);
}

// round 2
// speedup vs baseline: 1.0315x; 1.0315x over previous
#include <cuda_runtime.h>

#define BB   2
#define SS   2048
#define HH   16
#define DK   64
#define DM   1024
#define MTOT (BB*SS)   // 4096

// Scratch head-major Q/K/V: [B,H,S,Dk]
__device__ float g_q[BB*HH*SS*DK];
__device__ float g_k[BB*HH*SS*DK];
__device__ float g_v[BB*HH*SS*DK];

// ---------------------------------------------------------------------------
// QKV GEMM: C[m,n] = sum_k x[m,k] W[k,n] + bias[n], scattered to [B,H,S,Dk].
// 128x128 tile, K-step 16, 256 threads, 8x8 micro-tile.
// ---------------------------------------------------------------------------
__global__ __launch_bounds__(256) void qkv_gemm_kernel(
    const float* __restrict__ x, const float* __restrict__ W,
    const float* __restrict__ bias, int sel)
{
    __shared__ float As[16][132];   // [k][m]
    __shared__ float Bs[16][132];   // [k][n]

    float* out = (sel == 0) ? g_q : (sel == 1) ? g_k : g_v;

    const int t  = threadIdx.x;
    const int tx = t & 15;
    const int ty = t >> 4;
    const int m0 = blockIdx.y * 128;
    const int n0 = blockIdx.x * 128;

    const int arow = t >> 1;          // 0..127
    const int acg  = (t & 1) * 8;     // 0 or 8
    const int brow = t >> 4;          // 0..15
    const int bcg  = (t & 15) * 8;    // 0..120

    const float* xp = x + (size_t)(m0 + arow) * DM + acg;
    const float* wp = W + (size_t)brow * DM + n0 + bcg;

    float acc[8][8] = {};

    for (int k0 = 0; k0 < DM; k0 += 16) {
        float4 a0 = *(const float4*)(xp + k0);
        float4 a1 = *(const float4*)(xp + k0 + 4);
        float4 b0 = *(const float4*)(wp + (size_t)k0 * DM);
        float4 b1 = *(const float4*)(wp + (size_t)k0 * DM + 4);
        __syncthreads();
        As[acg + 0][arow] = a0.x; As[acg + 1][arow] = a0.y;
        As[acg + 2][arow] = a0.z; As[acg + 3][arow] = a0.w;
        As[acg + 4][arow] = a1.x; As[acg + 5][arow] = a1.y;
        As[acg + 6][arow] = a1.z; As[acg + 7][arow] = a1.w;
        *(float4*)&Bs[brow][bcg]     = b0;
        *(float4*)&Bs[brow][bcg + 4] = b1;
        __syncthreads();

        #pragma unroll
        for (int kk = 0; kk < 16; kk++) {
            float4 av0 = *(const float4*)&As[kk][ty * 8];
            float4 av1 = *(const float4*)&As[kk][ty * 8 + 4];
            float4 bv0 = *(const float4*)&Bs[kk][tx * 8];
            float4 bv1 = *(const float4*)&Bs[kk][tx * 8 + 4];
            float aa[8] = {av0.x, av0.y, av0.z, av0.w, av1.x, av1.y, av1.z, av1.w};
            float bb[8] = {bv0.x, bv0.y, bv0.z, bv0.w, bv1.x, bv1.y, bv1.z, bv1.w};
            #pragma unroll
            for (int i = 0; i < 8; i++)
                #pragma unroll
                for (int j = 0; j < 8; j++)
                    acc[i][j] += aa[i] * bb[j];
        }
    }

    // Epilogue: +bias, scatter to [B,H,S,Dk]; each thread's 8 cols lie in one head
    const int h     = (n0 + tx * 8) >> 6;
    const int dbase = (n0 + tx * 8) & 63;
    float4 bb0 = *(const float4*)(bias + n0 + tx * 8);
    float4 bb1 = *(const float4*)(bias + n0 + tx * 8 + 4);
    #pragma unroll
    for (int i = 0; i < 8; i++) {
        int m  = m0 + ty * 8 + i;
        int b_ = m >> 11;
        int s  = m & (SS - 1);
        float* op = out + (((size_t)(b_ * HH + h) * SS + s) * DK) + dbase;
        float4 r0, r1;
        r0.x = acc[i][0] + bb0.x; r0.y = acc[i][1] + bb0.y;
        r0.z = acc[i][2] + bb0.z; r0.w = acc[i][3] + bb0.w;
        r1.x = acc[i][4] + bb1.x; r1.y = acc[i][5] + bb1.y;
        r1.z = acc[i][6] + bb1.z; r1.w = acc[i][7] + bb1.w;
        *(float4*)op       = r0;
        *(float4*)(op + 4) = r1;
    }
}

// ---------------------------------------------------------------------------
// Flash-style attention, 128q x 128k tiles.
//   S stage: 16x16 threads, 8x8 micro (Q,K d-major in smem, ld=132)
//   P = exp(S) stored [q][k] ld=132 (float4 writes)
//   PV stage: 32x8 threads, 4q x 8d micro; P rows contiguous over k -> float4
//   denominator: tx2==0 lanes accumulate rowsums of P for free
// ---------------------------------------------------------------------------
#define QLD 132
#define PLD 132
#define ATTN_SMEM_FLOATS (64*QLD + 64*QLD + 128*64 + 128*PLD + 128)
#define ATTN_SMEM_BYTES  (ATTN_SMEM_FLOATS * 4)   // 168448 B

__global__ __launch_bounds__(256) void attn_kernel(float* __restrict__ out)
{
    extern __shared__ float sm[];
    float* Qs   = sm;                    // [d][q]  64x132
    float* Ks   = Qs + 64 * QLD;         // [d][k]  64x132
    float* Vs   = Ks + 64 * QLD;         // [k][d]  128x64
    float* Ps   = Vs + 128 * 64;         // [q][k]  128x132
    float* dsum = Ps + 128 * PLD;        // [128]

    const int t   = threadIdx.x;
    const int tx  = t & 15;
    const int ty  = t >> 4;
    const int tx2 = t & 7;
    const int ty2 = t >> 3;
    const int bh  = blockIdx.y;          // 0..31
    const int q0  = blockIdx.x * 128;

    const float* Qp = g_q + ((size_t)bh * SS + q0) * DK;
    const float* Kp = g_k + (size_t)bh * SS * DK;
    const float* Vp = g_v + (size_t)bh * SS * DK;

    // Load Q tile transposed ([d][q]) with 1/sqrt(Dk)=0.125 folded in
    #pragma unroll
    for (int rr = 0; rr < 8; rr++) {
        int row = (t >> 4) + rr * 16;    // 0..127 (query)
        int dg  = (t & 15) * 4;
        float4 v = *(const float4*)(Qp + (size_t)row * DK + dg);
        Qs[(dg + 0) * QLD + row] = v.x * 0.125f;
        Qs[(dg + 1) * QLD + row] = v.y * 0.125f;
        Qs[(dg + 2) * QLD + row] = v.z * 0.125f;
        Qs[(dg + 3) * QLD + row] = v.w * 0.125f;
    }

    float creg[4][8] = {};
    float dreg[4]    = {0.f, 0.f, 0.f, 0.f};

    for (int kt = 0; kt < SS / 128; kt++) {
        const float* kp = Kp + (size_t)kt * 128 * DK;
        const float* vp = Vp + (size_t)kt * 128 * DK;

        __syncthreads();   // prev iter's Ks/Vs/Ps consumers done (also covers Q stores)
        #pragma unroll
        for (int rr = 0; rr < 8; rr++) {
            int row = (t >> 4) + rr * 16;
            int dg  = (t & 15) * 4;
            float4 kv = *(const float4*)(kp + (size_t)row * DK + dg);
            Ks[(dg + 0) * QLD + row] = kv.x;
            Ks[(dg + 1) * QLD + row] = kv.y;
            Ks[(dg + 2) * QLD + row] = kv.z;
            Ks[(dg + 3) * QLD + row] = kv.w;
            *(float4*)&Vs[row * 64 + dg] = *(const float4*)(vp + (size_t)row * DK + dg);
        }
        __syncthreads();

        // ---- S = (Q/8) K^T : 8x8 micro ----
        float sreg[8][8] = {};
        #pragma unroll 4
        for (int d = 0; d < 64; d++) {
            float4 av0 = *(const float4*)&Qs[d * QLD + ty * 8];
            float4 av1 = *(const float4*)&Qs[d * QLD + ty * 8 + 4];
            float4 bv0 = *(const float4*)&Ks[d * QLD + tx * 8];
            float4 bv1 = *(const float4*)&Ks[d * QLD + tx * 8 + 4];
            float aa[8] = {av0.x, av0.y, av0.z, av0.w, av1.x, av1.y, av1.z, av1.w};
            float bb[8] = {bv0.x, bv0.y, bv0.z, bv0.w, bv1.x, bv1.y, bv1.z, bv1.w};
            #pragma unroll
            for (int i = 0; i < 8; i++)
                #pragma unroll
                for (int j = 0; j < 8; j++)
                    sreg[i][j] += aa[i] * bb[j];
        }

        // ---- P = exp(S), stored [q][k] ----
        #pragma unroll
        for (int i = 0; i < 8; i++) {
            float4 p0, p1;
            p0.x = __expf(sreg[i][0]); p0.y = __expf(sreg[i][1]);
            p0.z = __expf(sreg[i][2]); p0.w = __expf(sreg[i][3]);
            p1.x = __expf(sreg[i][4]); p1.y = __expf(sreg[i][5]);
            p1.z = __expf(sreg[i][6]); p1.w = __expf(sreg[i][7]);
            *(float4*)&Ps[(ty * 8 + i) * PLD + tx * 8]     = p0;
            *(float4*)&Ps[(ty * 8 + i) * PLD + tx * 8 + 4] = p1;
        }
        __syncthreads();

        // ---- ctx += P V (4q x 8d micro); denominator in tx2==0 lanes ----
        #pragma unroll 2
        for (int k = 0; k < 128; k += 4) {
            float4 a[4];
            #pragma unroll
            for (int i = 0; i < 4; i++)
                a[i] = *(const float4*)&Ps[(ty2 * 4 + i) * PLD + k];
            #pragma unroll
            for (int kk = 0; kk < 4; kk++) {
                float4 bv0 = *(const float4*)&Vs[(k + kk) * 64 + tx2 * 8];
                float4 bv1 = *(const float4*)&Vs[(k + kk) * 64 + tx2 * 8 + 4];
                float bb[8] = {bv0.x, bv0.y, bv0.z, bv0.w, bv1.x, bv1.y, bv1.z, bv1.w};
                float av[4] = {((const float*)&a[0])[kk], ((const float*)&a[1])[kk],
                               ((const float*)&a[2])[kk], ((const float*)&a[3])[kk]};
                #pragma unroll
                for (int i = 0; i < 4; i++)
                    #pragma unroll
                    for (int j = 0; j < 8; j++)
                        creg[i][j] += av[i] * bb[j];
            }
            if (tx2 == 0) {
                #pragma unroll
                for (int i = 0; i < 4; i++)
                    dreg[i] += a[i].x + a[i].y + a[i].z + a[i].w;
            }
        }
    }

    if (tx2 == 0) {
        #pragma unroll
        for (int i = 0; i < 4; i++) dsum[ty2 * 4 + i] = dreg[i];
    }
    __syncthreads();

    // out[b][s][h*64 + d]
    const int b_ = bh / HH;
    const int h  = bh % HH;
    #pragma unroll
    for (int i = 0; i < 4; i++) {
        float inv = 1.f / (dsum[ty2 * 4 + i] + 1e-8f);
        float4 r0, r1;
        r0.x = creg[i][0] * inv; r0.y = creg[i][1] * inv;
        r0.z = creg[i][2] * inv; r0.w = creg[i][3] * inv;
        r1.x = creg[i][4] * inv; r1.y = creg[i][5] * inv;
        r1.z = creg[i][6] * inv; r1.w = creg[i][7] * inv;
        size_t off = ((size_t)(b_ * SS + q0 + ty2 * 4 + i)) * DM + h * DK + tx2 * 8;
        *(float4*)(out + off)     = r0;
        *(float4*)(out + off + 4) = r1;
    }
}

// ---------------------------------------------------------------------------
extern "C" void kernel_launch(void* const* d_in, const int* in_sizes, int n_in,
                              void* d_out, int out_size)
{
    const float* x  = (const float*)d_in[0];
    const float* Wq = (const float*)d_in[1];
    const float* bq = (const float*)d_in[2];
    const float* Wk = (const float*)d_in[3];
    const float* bk = (const float*)d_in[4];
    const float* Wv = (const float*)d_in[5];
    const float* bv = (const float*)d_in[6];
    float* out = (float*)d_out;

    cudaFuncSetAttribute(attn_kernel,
                         cudaFuncAttributeMaxDynamicSharedMemorySize,
                         ATTN_SMEM_BYTES);

    dim3 ggrid(DM / 128, MTOT / 128);   // (8, 32)
    qkv_gemm_kernel<<<ggrid, 256>>>(x, Wq, bq, 0);
    qkv_gemm_kernel<<<ggrid, 256>>>(x, Wk, bk, 1);
    qkv_gemm_kernel<<<ggrid, 256>>>(x, Wv, bv, 2);

    dim3 agrid(SS / 128, BB * HH);      // (16, 32)
    attn_kernel<<<agrid, 256, ATTN_SMEM_BYTES>>>(out);
}

// round 4
// speedup vs baseline: 2.0386x; 1.9762x over previous
#include <cuda_runtime.h>
#include <cstdint>

#define BB   2
#define SS   2048
#define HH   16
#define DK   64
#define DM   1024
#define MTOT (BB*SS)   // 4096

__device__ float g_q[BB*HH*SS*DK];
__device__ float g_k[BB*HH*SS*DK];
__device__ float g_v[BB*HH*SS*DK];

// ---------------------------------------------------------------------------
__device__ __forceinline__ uint32_t f2tf32(float f) {
    uint32_t r;
    asm("cvt.rna.tf32.f32 %0, %1;" : "=r"(r) : "f"(f));
    return r;
}
__device__ __forceinline__ void mma8(float c[4], const uint32_t a[4],
                                     const uint32_t b[2]) {
    asm volatile(
        "mma.sync.aligned.m16n8k8.row.col.f32.tf32.tf32.f32 "
        "{%0,%1,%2,%3}, {%4,%5,%6,%7}, {%8,%9}, {%0,%1,%2,%3};"
        : "+f"(c[0]), "+f"(c[1]), "+f"(c[2]), "+f"(c[3])
        : "r"(a[0]), "r"(a[1]), "r"(a[2]), "r"(a[3]), "r"(b[0]), "r"(b[1]));
}

// ===========================================================================
// QKV GEMM, tf32 mma.sync: CTA 128x128, 8 warps (2m x 4n), warp 64x32
// ===========================================================================
__global__ __launch_bounds__(256, 1) void qkv_gemm_tc(
    const float* __restrict__ x, const float* __restrict__ W,
    const float* __restrict__ bias, int sel)
{
    __shared__ uint32_t As[128][20];   // [m][k] tf32, pad->conflict-free frags
    __shared__ uint32_t Ws[16][132];   // [k][n] tf32

    float* outp = (sel == 0) ? g_q : (sel == 1) ? g_k : g_v;

    const int t    = threadIdx.x;
    const int wid  = t >> 5;
    const int lane = t & 31;
    const int g    = lane >> 2;    // groupID 0..7
    const int tg   = lane & 3;     // thread-in-group
    const int wm   = wid & 1;      // 2 m-sections of 64
    const int wn   = wid >> 1;     // 4 n-sections of 32
    const int m0   = blockIdx.y * 128;
    const int n0   = blockIdx.x * 128;

    const int xrow = t >> 1, xcg = (t & 1) * 8;
    const int wrow = t >> 4, wcg = (t & 15) * 8;

    float acc[4][4][4] = {};

    for (int k0 = 0; k0 < DM; k0 += 16) {
        float4 xv0 = *(const float4*)(x + (size_t)(m0 + xrow) * DM + k0 + xcg);
        float4 xv1 = *(const float4*)(x + (size_t)(m0 + xrow) * DM + k0 + xcg + 4);
        float4 wv0 = *(const float4*)(W + (size_t)(k0 + wrow) * DM + n0 + wcg);
        float4 wv1 = *(const float4*)(W + (size_t)(k0 + wrow) * DM + n0 + wcg + 4);
        __syncthreads();
        *(uint4*)&As[xrow][xcg] =
            make_uint4(f2tf32(xv0.x), f2tf32(xv0.y), f2tf32(xv0.z), f2tf32(xv0.w));
        *(uint4*)&As[xrow][xcg + 4] =
            make_uint4(f2tf32(xv1.x), f2tf32(xv1.y), f2tf32(xv1.z), f2tf32(xv1.w));
        *(uint4*)&Ws[wrow][wcg] =
            make_uint4(f2tf32(wv0.x), f2tf32(wv0.y), f2tf32(wv0.z), f2tf32(wv0.w));
        *(uint4*)&Ws[wrow][wcg + 4] =
            make_uint4(f2tf32(wv1.x), f2tf32(wv1.y), f2tf32(wv1.z), f2tf32(wv1.w));
        __syncthreads();

        #pragma unroll
        for (int kk = 0; kk < 16; kk += 8) {
            uint32_t a[4][4], b[4][2];
            #pragma unroll
            for (int mi = 0; mi < 4; mi++) {
                int r = wm * 64 + mi * 16 + g;
                a[mi][0] = As[r][kk + tg];
                a[mi][1] = As[r + 8][kk + tg];
                a[mi][2] = As[r][kk + tg + 4];
                a[mi][3] = As[r + 8][kk + tg + 4];
            }
            #pragma unroll
            for (int ni = 0; ni < 4; ni++) {
                int c = wn * 32 + ni * 8 + g;
                b[ni][0] = Ws[kk + tg][c];
                b[ni][1] = Ws[kk + tg + 4][c];
            }
            #pragma unroll
            for (int mi = 0; mi < 4; mi++)
                #pragma unroll
                for (int ni = 0; ni < 4; ni++)
                    mma8(acc[mi][ni], a[mi], b[ni]);
        }
    }

    // epilogue: +bias, scatter to head-major [B,H,S,Dk]
    const int h = (n0 + wn * 32) >> 6;     // warp's 32 cols lie in one head
    #pragma unroll
    for (int ni = 0; ni < 4; ni++) {
        int gcol = n0 + wn * 32 + ni * 8 + 2 * tg;
        int d    = gcol & 63;
        float b0 = bias[gcol], b1 = bias[gcol + 1];
        #pragma unroll
        for (int mi = 0; mi < 4; mi++) {
            int r0 = m0 + wm * 64 + mi * 16 + g;
            int r1 = r0 + 8;
            int b_0 = r0 >> 11, s0 = r0 & (SS - 1);
            int b_1 = r1 >> 11, s1 = r1 & (SS - 1);
            float2 v0 = make_float2(acc[mi][ni][0] + b0, acc[mi][ni][1] + b1);
            float2 v1 = make_float2(acc[mi][ni][2] + b0, acc[mi][ni][3] + b1);
            *(float2*)(outp + (((size_t)(b_0 * HH + h) * SS + s0) * DK) + d) = v0;
            *(float2*)(outp + (((size_t)(b_1 * HH + h) * SS + s1) * DK) + d) = v1;
        }
    }
}

// ===========================================================================
// Flash attention, tf32 mma.sync.
// CTA = (b,h) x 128-query tile, 256 threads (8 warps x 16q band).
//  S:  warp 16x128 (raw-exp softmax in C-frags; rowsum per-thread + quad shfl)
//  PV: warp 16x64, P rows read == P rows written by same warp (no extra sync)
// ===========================================================================
#define QLD 68
#define PLD 132
#define SMQ 0
#define SMK (128*QLD)
#define SMV (2*128*QLD)
#define SMP (3*128*QLD)
#define ATTN_SMEM ((3*128*QLD + 128*PLD) * 4)   // 172032 B

__global__ __launch_bounds__(256, 1) void attn_tc(float* __restrict__ out)
{
    extern __shared__ uint32_t sm[];
    uint32_t* Qs = sm + SMQ;   // [q][d]   128x68
    uint32_t* Ks = sm + SMK;   // [key][d] 128x68
    uint32_t* Vs = sm + SMV;   // [key][d] 128x68
    uint32_t* Ps = sm + SMP;   // [q][key] 128x132

    const int t    = threadIdx.x;
    const int wid  = t >> 5;
    const int lane = t & 31;
    const int g    = lane >> 2;
    const int tg   = lane & 3;
    const int bh   = blockIdx.y;
    const int q0   = blockIdx.x * 128;

    const float* Qp = g_q + ((size_t)bh * SS + q0) * DK;
    const float* Kp = g_k + (size_t)bh * SS * DK;
    const float* Vp = g_v + (size_t)bh * SS * DK;

    // ---- load Q tile (scaled 1/8, tf32) : row t/2, 32 cols each ----
    {
        const int row = t >> 1, c0 = (t & 1) * 32;
        const float* qp = Qp + (size_t)row * DK + c0;
        #pragma unroll
        for (int c = 0; c < 32; c += 4) {
            float4 v = *(const float4*)(qp + c);
            *(uint4*)&Qs[row * QLD + c0 + c] =
                make_uint4(f2tf32(v.x * 0.125f), f2tf32(v.y * 0.125f),
                           f2tf32(v.z * 0.125f), f2tf32(v.w * 0.125f));
        }
    }

    float cacc[8][4] = {};             // ctx frags: 16q x 64d warp tile
    float rs0 = 0.f, rs1 = 0.f;        // rowsum partials (rows g, g+8)
    const int arow = wid * 16 + g;     // this thread's base q-row in band

    for (int kt = 0; kt < SS / 128; kt++) {
        // ---- load K,V tiles ----
        const int row = t >> 1, c0 = (t & 1) * 32;
        const float* kp = Kp + (size_t)(kt * 128 + row) * DK + c0;
        const float* vp = Vp + (size_t)(kt * 128 + row) * DK + c0;
        float4 kv[8], vv[8];
        #pragma unroll
        for (int c = 0; c < 8; c++) {
            kv[c] = *(const float4*)(kp + c * 4);
            vv[c] = *(const float4*)(vp + c * 4);
        }
        __syncthreads();   // prev iter's consumers of Ks/Vs done
        #pragma unroll
        for (int c = 0; c < 8; c++) {
            *(uint4*)&Ks[row * QLD + c0 + c * 4] =
                make_uint4(f2tf32(kv[c].x), f2tf32(kv[c].y),
                           f2tf32(kv[c].z), f2tf32(kv[c].w));
            *(uint4*)&Vs[row * QLD + c0 + c * 4] =
                make_uint4(f2tf32(vv[c].x), f2tf32(vv[c].y),
                           f2tf32(vv[c].z), f2tf32(vv[c].w));
        }
        __syncthreads();

        // ---- S = (Q/8) K^T : 16q x 128k per warp ----
        float sc[16][4] = {};
        #pragma unroll
        for (int k0 = 0; k0 < 8; k0++) {
            uint32_t a[4];
            a[0] = Qs[arow * QLD + k0 * 8 + tg];
            a[1] = Qs[(arow + 8) * QLD + k0 * 8 + tg];
            a[2] = Qs[arow * QLD + k0 * 8 + tg + 4];
            a[3] = Qs[(arow + 8) * QLD + k0 * 8 + tg + 4];
            #pragma unroll
            for (int ni = 0; ni < 16; ni++) {
                uint32_t b[2];
                b[0] = Ks[(ni * 8 + g) * QLD + k0 * 8 + tg];
                b[1] = Ks[(ni * 8 + g) * QLD + k0 * 8 + tg + 4];
                mma8(sc[ni], a, b);
            }
        }

        // ---- P = exp(S) -> Ps (tf32); rowsum partials ----
        #pragma unroll
        for (int ni = 0; ni < 16; ni++) {
            float e0 = __expf(sc[ni][0]);
            float e1 = __expf(sc[ni][1]);
            float e2 = __expf(sc[ni][2]);
            float e3 = __expf(sc[ni][3]);
            rs0 += e0 + e1;
            rs1 += e2 + e3;
            int col = ni * 8 + 2 * tg;
            *(uint2*)&Ps[arow * PLD + col]       = make_uint2(f2tf32(e0), f2tf32(e1));
            *(uint2*)&Ps[(arow + 8) * PLD + col] = make_uint2(f2tf32(e2), f2tf32(e3));
        }
        __syncwarp();   // P band produced & consumed by this warp only

        // ---- ctx += P V : 16q x 64d per warp ----
        #pragma unroll
        for (int k0 = 0; k0 < 16; k0++) {
            uint32_t a[4];
            a[0] = Ps[arow * PLD + k0 * 8 + tg];
            a[1] = Ps[(arow + 8) * PLD + k0 * 8 + tg];
            a[2] = Ps[arow * PLD + k0 * 8 + tg + 4];
            a[3] = Ps[(arow + 8) * PLD + k0 * 8 + tg + 4];
            #pragma unroll
            for (int ni = 0; ni < 8; ni++) {
                uint32_t b[2];
                b[0] = Vs[(k0 * 8 + tg) * QLD + ni * 8 + g];
                b[1] = Vs[(k0 * 8 + tg + 4) * QLD + ni * 8 + g];
                mma8(cacc[ni], a, b);
            }
        }
    }

    // ---- rowsum quad-reduce, normalize, store ----
    rs0 += __shfl_xor_sync(0xFFFFFFFF, rs0, 1);
    rs0 += __shfl_xor_sync(0xFFFFFFFF, rs0, 2);
    rs1 += __shfl_xor_sync(0xFFFFFFFF, rs1, 1);
    rs1 += __shfl_xor_sync(0xFFFFFFFF, rs1, 2);
    const float inv0 = 1.f / (rs0 + 1e-8f);
    const float inv1 = 1.f / (rs1 + 1e-8f);

    const int b_ = bh / HH;
    const int h  = bh % HH;
    const int r0 = q0 + arow;
    const int r1 = r0 + 8;
    float* o0 = out + (size_t)(b_ * SS + r0) * DM + h * DK;
    float* o1 = out + (size_t)(b_ * SS + r1) * DM + h * DK;
    #pragma unroll
    for (int ni = 0; ni < 8; ni++) {
        int d = ni * 8 + 2 * tg;
        *(float2*)(o0 + d) = make_float2(cacc[ni][0] * inv0, cacc[ni][1] * inv0);
        *(float2*)(o1 + d) = make_float2(cacc[ni][2] * inv1, cacc[ni][3] * inv1);
    }
}

// ===========================================================================
extern "C" void kernel_launch(void* const* d_in, const int* in_sizes, int n_in,
                              void* d_out, int out_size)
{
    const float* x  = (const float*)d_in[0];
    const float* Wq = (const float*)d_in[1];
    const float* bq = (const float*)d_in[2];
    const float* Wk = (const float*)d_in[3];
    const float* bk = (const float*)d_in[4];
    const float* Wv = (const float*)d_in[5];
    const float* bv = (const float*)d_in[6];
    float* out = (float*)d_out;

    cudaFuncSetAttribute(attn_tc,
                         cudaFuncAttributeMaxDynamicSharedMemorySize, ATTN_SMEM);

    dim3 ggrid(DM / 128, MTOT / 128);   // (8, 32)
    qkv_gemm_tc<<<ggrid, 256>>>(x, Wq, bq, 0);
    qkv_gemm_tc<<<ggrid, 256>>>(x, Wk, bk, 1);
    qkv_gemm_tc<<<ggrid, 256>>>(x, Wv, bv, 2);

    dim3 agrid(SS / 128, BB * HH);      // (16, 32)
    attn_tc<<<agrid, 256, ATTN_SMEM>>>(out);
}

// round 5
// speedup vs baseline: 2.6542x; 1.3020x over previous
#include <cuda_runtime.h>
#include <cstdint>

#define BB   2
#define SS   2048
#define HH   16
#define DK   64
#define DM   1024
#define MTOT (BB*SS)   // 4096

__device__ float g_q[BB*HH*SS*DK];
__device__ float g_k[BB*HH*SS*DK];
__device__ float g_v[BB*HH*SS*DK];

// ---------------------------------------------------------------------------
__device__ __forceinline__ uint32_t f2tf32(float f) {
    uint32_t r;
    asm("cvt.rna.tf32.f32 %0, %1;" : "=r"(r) : "f"(f));
    return r;
}
__device__ __forceinline__ uint32_t smem_u32(const void* p) {
    uint32_t a;
    asm("{ .reg .u64 t; cvta.to.shared.u64 t, %1; cvt.u32.u64 %0, t; }"
        : "=r"(a) : "l"(p));
    return a;
}
__device__ __forceinline__ void mma8(float c[4], const uint32_t* a,
                                     const uint32_t* b) {
    asm volatile(
        "mma.sync.aligned.m16n8k8.row.col.f32.tf32.tf32.f32 "
        "{%0,%1,%2,%3}, {%4,%5,%6,%7}, {%8,%9}, {%0,%1,%2,%3};"
        : "+f"(c[0]), "+f"(c[1]), "+f"(c[2]), "+f"(c[3])
        : "r"(a[0]), "r"(a[1]), "r"(a[2]), "r"(a[3]), "r"(b[0]), "r"(b[1]));
}
__device__ __forceinline__ void ldsm4(uint32_t r[4], uint32_t addr) {
    asm volatile("ldmatrix.sync.aligned.m8n8.x4.shared.b16 {%0,%1,%2,%3}, [%4];"
                 : "=r"(r[0]), "=r"(r[1]), "=r"(r[2]), "=r"(r[3]) : "r"(addr));
}

// ===========================================================================
// QKV GEMM, tf32 mma.sync: CTA 128x128, 8 warps (2m x 4n), warp 64x32.
// Double-buffered smem + gmem prefetch + ldmatrix A-frags.
// ===========================================================================
__global__ __launch_bounds__(256, 2) void qkv_gemm_tc(
    const float* __restrict__ x, const float* __restrict__ W,
    const float* __restrict__ bias, int sel)
{
    __shared__ uint32_t As[2][128][20];   // [m][k] tf32
    __shared__ uint32_t Ws[2][16][132];   // [k][n] tf32

    float* outp = (sel == 0) ? g_q : (sel == 1) ? g_k : g_v;

    const int t    = threadIdx.x;
    const int wid  = t >> 5;
    const int lane = t & 31;
    const int g    = lane >> 2;
    const int tg   = lane & 3;
    const int wm   = wid & 1;
    const int wn   = wid >> 1;
    const int m0   = blockIdx.y * 128;
    const int n0   = blockIdx.x * 128;

    const int xrow = t >> 1, xcg = (t & 1) * 8;
    const int wrow = t >> 4, wcg = (t & 15) * 8;

    const int lane15  = lane & 15;
    const int laneHi4 = ((lane >> 4) & 1) * 4;
    // A-frag ldmatrix lane address (words): row (wm*64 + mi*16 + lane15), col kk + laneHi4
    const uint32_t as_base0 = smem_u32(&As[0][0][0]);
    const uint32_t as_base1 = smem_u32(&As[1][0][0]);
    const uint32_t a_lane   = (uint32_t)(((wm * 64 + lane15) * 20 + laneHi4) * 4);

    float acc[4][4][4] = {};
    float4 xv0, xv1, wv0, wv1;

    // prologue: chunk 0 -> regs -> smem[0]
    xv0 = *(const float4*)(x + (size_t)(m0 + xrow) * DM + xcg);
    xv1 = *(const float4*)(x + (size_t)(m0 + xrow) * DM + xcg + 4);
    wv0 = *(const float4*)(W + (size_t)wrow * DM + n0 + wcg);
    wv1 = *(const float4*)(W + (size_t)wrow * DM + n0 + wcg + 4);
    *(uint4*)&As[0][xrow][xcg] =
        make_uint4(f2tf32(xv0.x), f2tf32(xv0.y), f2tf32(xv0.z), f2tf32(xv0.w));
    *(uint4*)&As[0][xrow][xcg + 4] =
        make_uint4(f2tf32(xv1.x), f2tf32(xv1.y), f2tf32(xv1.z), f2tf32(xv1.w));
    *(uint4*)&Ws[0][wrow][wcg] =
        make_uint4(f2tf32(wv0.x), f2tf32(wv0.y), f2tf32(wv0.z), f2tf32(wv0.w));
    *(uint4*)&Ws[0][wrow][wcg + 4] =
        make_uint4(f2tf32(wv1.x), f2tf32(wv1.y), f2tf32(wv1.z), f2tf32(wv1.w));
    __syncthreads();

    for (int it = 0; it < DM / 16; it++) {
        const int cur = it & 1;
        const int nxt = cur ^ 1;
        if (it + 1 < DM / 16) {
            int k0 = (it + 1) * 16;
            xv0 = *(const float4*)(x + (size_t)(m0 + xrow) * DM + k0 + xcg);
            xv1 = *(const float4*)(x + (size_t)(m0 + xrow) * DM + k0 + xcg + 4);
            wv0 = *(const float4*)(W + (size_t)(k0 + wrow) * DM + n0 + wcg);
            wv1 = *(const float4*)(W + (size_t)(k0 + wrow) * DM + n0 + wcg + 4);
        }

        const uint32_t as_b = (cur ? as_base1 : as_base0) + a_lane;
        #pragma unroll
        for (int kk = 0; kk < 16; kk += 8) {
            uint32_t a[4][4], b[4][2];
            #pragma unroll
            for (int mi = 0; mi < 4; mi++)
                ldsm4(a[mi], as_b + (uint32_t)((mi * 16 * 20 + kk) * 4));
            #pragma unroll
            for (int ni = 0; ni < 4; ni++) {
                int c = wn * 32 + ni * 8 + g;
                b[ni][0] = Ws[cur][kk + tg][c];
                b[ni][1] = Ws[cur][kk + tg + 4][c];
            }
            #pragma unroll
            for (int mi = 0; mi < 4; mi++)
                #pragma unroll
                for (int ni = 0; ni < 4; ni++)
                    mma8(acc[mi][ni], a[mi], b[ni]);
        }

        if (it + 1 < DM / 16) {
            *(uint4*)&As[nxt][xrow][xcg] =
                make_uint4(f2tf32(xv0.x), f2tf32(xv0.y), f2tf32(xv0.z), f2tf32(xv0.w));
            *(uint4*)&As[nxt][xrow][xcg + 4] =
                make_uint4(f2tf32(xv1.x), f2tf32(xv1.y), f2tf32(xv1.z), f2tf32(xv1.w));
            *(uint4*)&Ws[nxt][wrow][wcg] =
                make_uint4(f2tf32(wv0.x), f2tf32(wv0.y), f2tf32(wv0.z), f2tf32(wv0.w));
            *(uint4*)&Ws[nxt][wrow][wcg + 4] =
                make_uint4(f2tf32(wv1.x), f2tf32(wv1.y), f2tf32(wv1.z), f2tf32(wv1.w));
            __syncthreads();
        }
    }

    // epilogue: +bias, scatter to head-major [B,H,S,Dk]
    const int h = (n0 + wn * 32) >> 6;
    #pragma unroll
    for (int ni = 0; ni < 4; ni++) {
        int gcol = n0 + wn * 32 + ni * 8 + 2 * tg;
        int d    = gcol & 63;
        float b0 = bias[gcol], b1 = bias[gcol + 1];
        #pragma unroll
        for (int mi = 0; mi < 4; mi++) {
            int r0 = m0 + wm * 64 + mi * 16 + g;
            int r1 = r0 + 8;
            int b_0 = r0 >> 11, s0 = r0 & (SS - 1);
            int b_1 = r1 >> 11, s1 = r1 & (SS - 1);
            *(float2*)(outp + (((size_t)(b_0 * HH + h) * SS + s0) * DK) + d) =
                make_float2(acc[mi][ni][0] + b0, acc[mi][ni][1] + b1);
            *(float2*)(outp + (((size_t)(b_1 * HH + h) * SS + s1) * DK) + d) =
                make_float2(acc[mi][ni][2] + b0, acc[mi][ni][3] + b1);
        }
    }
}

// ===========================================================================
// Flash attention, tf32 mma.sync + ldmatrix fragment loads.
// CTA = (b,h) x 128-query tile, 256 threads, 8 warps x 16q band.
// V stored TRANSPOSED (Vt[d][key]) so PV B-frags are ldmatrix rows.
// ===========================================================================
#define QLD 68
#define PLD 132
#define VLD 132
#define SMQ_B  0
#define SMK_B  (128*QLD*4)                 // 34816
#define SMVT_B (SMK_B + 128*QLD*4)         // 69632
#define SMP_B  (SMVT_B + 64*VLD*4)         // 103424
#define ATTN_SMEM (SMP_B + 128*PLD*4)      // 171008

__global__ __launch_bounds__(256, 1) void attn_tc(float* __restrict__ out)
{
    extern __shared__ char smem[];
    const uint32_t sb = smem_u32(smem);
    uint32_t* Qs = (uint32_t*)(smem + SMQ_B);    // [q][d]   128x68
    uint32_t* Ks = (uint32_t*)(smem + SMK_B);    // [key][d] 128x68
    uint32_t* Vt = (uint32_t*)(smem + SMVT_B);   // [d][key] 64x132
    uint32_t* Ps = (uint32_t*)(smem + SMP_B);    // [q][key] 128x132

    const int t    = threadIdx.x;
    const int wid  = t >> 5;
    const int lane = t & 31;
    const int g    = lane >> 2;
    const int tg   = lane & 3;
    const int bh   = blockIdx.y;
    const int q0   = blockIdx.x * 128;

    const float* Qp = g_q + ((size_t)bh * SS + q0) * DK;
    const float* Kp = g_k + (size_t)bh * SS * DK;
    const float* Vp = g_v + (size_t)bh * SS * DK;

    // ---- load Q tile (scaled 1/8, tf32) ----
    {
        const int row = t >> 1, c0 = (t & 1) * 32;
        const float* qp = Qp + (size_t)row * DK + c0;
        #pragma unroll
        for (int c = 0; c < 32; c += 4) {
            float4 v = *(const float4*)(qp + c);
            *(uint4*)&Qs[row * QLD + c0 + c] =
                make_uint4(f2tf32(v.x * 0.125f), f2tf32(v.y * 0.125f),
                           f2tf32(v.z * 0.125f), f2tf32(v.w * 0.125f));
        }
    }

    // ldmatrix lane-static addresses (bytes)
    const int lane15  = lane & 15;
    const int lane7   = lane & 7;
    const int laneHi  = (lane >> 4) & 1;
    const int laneMid = (lane >> 3) & 1;
    const int arow0   = wid * 16;
    const uint32_t qa = sb + SMQ_B  + (uint32_t)(((arow0 + lane15) * QLD + laneHi * 4) * 4);
    const uint32_t ka = sb + SMK_B  + (uint32_t)(((laneHi * 8 + lane7) * QLD + laneMid * 4) * 4);
    const uint32_t pa = sb + SMP_B  + (uint32_t)(((arow0 + lane15) * PLD + laneHi * 4) * 4);
    const uint32_t va = sb + SMVT_B + (uint32_t)(((laneHi * 8 + lane7) * VLD + laneMid * 4) * 4);

    float cacc[8][4] = {};
    float rs0 = 0.f, rs1 = 0.f;
    const int arow = arow0 + g;

    for (int kt = 0; kt < SS / 128; kt++) {
        // ---- load K,V tiles (V transposed into Vt) ----
        const int row = t >> 1, c0 = (t & 1) * 32;
        const float* kp = Kp + (size_t)(kt * 128 + row) * DK + c0;
        const float* vp = Vp + (size_t)(kt * 128 + row) * DK + c0;
        float4 kv[8], vv[8];
        #pragma unroll
        for (int c = 0; c < 8; c++) {
            kv[c] = *(const float4*)(kp + c * 4);
            vv[c] = *(const float4*)(vp + c * 4);
        }
        __syncthreads();
        #pragma unroll
        for (int c = 0; c < 8; c++) {
            *(uint4*)&Ks[row * QLD + c0 + c * 4] =
                make_uint4(f2tf32(kv[c].x), f2tf32(kv[c].y),
                           f2tf32(kv[c].z), f2tf32(kv[c].w));
            int d = c0 + c * 4;
            Vt[(d + 0) * VLD + row] = f2tf32(vv[c].x);
            Vt[(d + 1) * VLD + row] = f2tf32(vv[c].y);
            Vt[(d + 2) * VLD + row] = f2tf32(vv[c].z);
            Vt[(d + 3) * VLD + row] = f2tf32(vv[c].w);
        }
        __syncthreads();

        // ---- S = (Q/8) K^T : 16q x 128k per warp ----
        float sc[16][4] = {};
        #pragma unroll
        for (int k0 = 0; k0 < 64; k0 += 8) {
            uint32_t a[4];
            ldsm4(a, qa + (uint32_t)(k0 * 4));
            #pragma unroll
            for (int ni = 0; ni < 16; ni += 2) {
                uint32_t b[4];
                ldsm4(b, ka + (uint32_t)((ni * 8 * QLD + k0) * 4));
                mma8(sc[ni],     a, b);
                mma8(sc[ni + 1], a, b + 2);
            }
        }

        // ---- P = exp(S) -> Ps (tf32); rowsum partials ----
        #pragma unroll
        for (int ni = 0; ni < 16; ni++) {
            float e0 = __expf(sc[ni][0]);
            float e1 = __expf(sc[ni][1]);
            float e2 = __expf(sc[ni][2]);
            float e3 = __expf(sc[ni][3]);
            rs0 += e0 + e1;
            rs1 += e2 + e3;
            int col = ni * 8 + 2 * tg;
            *(uint2*)&Ps[arow * PLD + col]       = make_uint2(f2tf32(e0), f2tf32(e1));
            *(uint2*)&Ps[(arow + 8) * PLD + col] = make_uint2(f2tf32(e2), f2tf32(e3));
        }
        __syncwarp();   // P band produced & consumed by this warp only

        // ---- ctx += P V : 16q x 64d per warp ----
        #pragma unroll
        for (int k0 = 0; k0 < 128; k0 += 8) {
            uint32_t a[4];
            ldsm4(a, pa + (uint32_t)(k0 * 4));
            #pragma unroll
            for (int ni = 0; ni < 8; ni += 2) {
                uint32_t b[4];
                ldsm4(b, va + (uint32_t)((ni * 8 * VLD + k0) * 4));
                mma8(cacc[ni],     a, b);
                mma8(cacc[ni + 1], a, b + 2);
            }
        }
    }

    // ---- rowsum quad-reduce, normalize, store ----
    rs0 += __shfl_xor_sync(0xFFFFFFFF, rs0, 1);
    rs0 += __shfl_xor_sync(0xFFFFFFFF, rs0, 2);
    rs1 += __shfl_xor_sync(0xFFFFFFFF, rs1, 1);
    rs1 += __shfl_xor_sync(0xFFFFFFFF, rs1, 2);
    const float inv0 = 1.f / (rs0 + 1e-8f);
    const float inv1 = 1.f / (rs1 + 1e-8f);

    const int b_ = bh / HH;
    const int h  = bh % HH;
    const int r0 = q0 + arow;
    const int r1 = r0 + 8;
    float* o0 = out + (size_t)(b_ * SS + r0) * DM + h * DK;
    float* o1 = out + (size_t)(b_ * SS + r1) * DM + h * DK;
    #pragma unroll
    for (int ni = 0; ni < 8; ni++) {
        int d = ni * 8 + 2 * tg;
        *(float2*)(o0 + d) = make_float2(cacc[ni][0] * inv0, cacc[ni][1] * inv0);
        *(float2*)(o1 + d) = make_float2(cacc[ni][2] * inv1, cacc[ni][3] * inv1);
    }
}

// ===========================================================================
extern "C" void kernel_launch(void* const* d_in, const int* in_sizes, int n_in,
                              void* d_out, int out_size)
{
    const float* x  = (const float*)d_in[0];
    const float* Wq = (const float*)d_in[1];
    const float* bq = (const float*)d_in[2];
    const float* Wk = (const float*)d_in[3];
    const float* bk = (const float*)d_in[4];
    const float* Wv = (const float*)d_in[5];
    const float* bv = (const float*)d_in[6];
    float* out = (float*)d_out;

    cudaFuncSetAttribute(attn_tc,
                         cudaFuncAttributeMaxDynamicSharedMemorySize, ATTN_SMEM);

    dim3 ggrid(DM / 128, MTOT / 128);   // (8, 32)
    qkv_gemm_tc<<<ggrid, 256>>>(x, Wq, bq, 0);
    qkv_gemm_tc<<<ggrid, 256>>>(x, Wk, bk, 1);
    qkv_gemm_tc<<<ggrid, 256>>>(x, Wv, bv, 2);

    dim3 agrid(SS / 128, BB * HH);      // (16, 32)
    attn_tc<<<agrid, 256, ATTN_SMEM>>>(out);
}

// round 6
// speedup vs baseline: 3.0734x; 1.1579x over previous
#include <cuda_runtime.h>
#include <cstdint>

#define BB   2
#define SS   2048
#define HH   16
#define DK   64
#define DM   1024
#define MTOT (BB*SS)   // 4096

__device__ float g_q[BB*HH*SS*DK];
__device__ float g_k[BB*HH*SS*DK];
__device__ float g_v[BB*HH*SS*DK];

// ---------------------------------------------------------------------------
__device__ __forceinline__ uint32_t f2tf32(float f) {
    uint32_t r;
    asm("cvt.rna.tf32.f32 %0, %1;" : "=r"(r) : "f"(f));
    return r;
}
__device__ __forceinline__ uint32_t smem_u32(const void* p) {
    uint32_t a;
    asm("{ .reg .u64 t; cvta.to.shared.u64 t, %1; cvt.u32.u64 %0, t; }"
        : "=r"(a) : "l"(p));
    return a;
}
__device__ __forceinline__ void mma8(float c[4], const uint32_t* a,
                                     const uint32_t* b) {
    asm volatile(
        "mma.sync.aligned.m16n8k8.row.col.f32.tf32.tf32.f32 "
        "{%0,%1,%2,%3}, {%4,%5,%6,%7}, {%8,%9}, {%0,%1,%2,%3};"
        : "+f"(c[0]), "+f"(c[1]), "+f"(c[2]), "+f"(c[3])
        : "r"(a[0]), "r"(a[1]), "r"(a[2]), "r"(a[3]), "r"(b[0]), "r"(b[1]));
}
__device__ __forceinline__ void ldsm4(uint32_t r[4], uint32_t addr) {
    asm volatile("ldmatrix.sync.aligned.m8n8.x4.shared.b16 {%0,%1,%2,%3}, [%4];"
                 : "=r"(r[0]), "=r"(r[1]), "=r"(r[2]), "=r"(r[3]) : "r"(addr));
}

// ===========================================================================
// QKV GEMM (unchanged from R5): CTA 128x128, 8 warps, double-buffered+ldmatrix
// ===========================================================================
__global__ __launch_bounds__(256, 2) void qkv_gemm_tc(
    const float* __restrict__ x, const float* __restrict__ W,
    const float* __restrict__ bias, int sel)
{
    __shared__ uint32_t As[2][128][20];
    __shared__ uint32_t Ws[2][16][132];

    float* outp = (sel == 0) ? g_q : (sel == 1) ? g_k : g_v;

    const int t    = threadIdx.x;
    const int wid  = t >> 5;
    const int lane = t & 31;
    const int g    = lane >> 2;
    const int tg   = lane & 3;
    const int wm   = wid & 1;
    const int wn   = wid >> 1;
    const int m0   = blockIdx.y * 128;
    const int n0   = blockIdx.x * 128;

    const int xrow = t >> 1, xcg = (t & 1) * 8;
    const int wrow = t >> 4, wcg = (t & 15) * 8;

    const int lane15  = lane & 15;
    const int laneHi4 = ((lane >> 4) & 1) * 4;
    const uint32_t as_base0 = smem_u32(&As[0][0][0]);
    const uint32_t as_base1 = smem_u32(&As[1][0][0]);
    const uint32_t a_lane   = (uint32_t)(((wm * 64 + lane15) * 20 + laneHi4) * 4);

    float acc[4][4][4] = {};
    float4 xv0, xv1, wv0, wv1;

    xv0 = *(const float4*)(x + (size_t)(m0 + xrow) * DM + xcg);
    xv1 = *(const float4*)(x + (size_t)(m0 + xrow) * DM + xcg + 4);
    wv0 = *(const float4*)(W + (size_t)wrow * DM + n0 + wcg);
    wv1 = *(const float4*)(W + (size_t)wrow * DM + n0 + wcg + 4);
    *(uint4*)&As[0][xrow][xcg] =
        make_uint4(f2tf32(xv0.x), f2tf32(xv0.y), f2tf32(xv0.z), f2tf32(xv0.w));
    *(uint4*)&As[0][xrow][xcg + 4] =
        make_uint4(f2tf32(xv1.x), f2tf32(xv1.y), f2tf32(xv1.z), f2tf32(xv1.w));
    *(uint4*)&Ws[0][wrow][wcg] =
        make_uint4(f2tf32(wv0.x), f2tf32(wv0.y), f2tf32(wv0.z), f2tf32(wv0.w));
    *(uint4*)&Ws[0][wrow][wcg + 4] =
        make_uint4(f2tf32(wv1.x), f2tf32(wv1.y), f2tf32(wv1.z), f2tf32(wv1.w));
    __syncthreads();

    for (int it = 0; it < DM / 16; it++) {
        const int cur = it & 1;
        const int nxt = cur ^ 1;
        if (it + 1 < DM / 16) {
            int k0 = (it + 1) * 16;
            xv0 = *(const float4*)(x + (size_t)(m0 + xrow) * DM + k0 + xcg);
            xv1 = *(const float4*)(x + (size_t)(m0 + xrow) * DM + k0 + xcg + 4);
            wv0 = *(const float4*)(W + (size_t)(k0 + wrow) * DM + n0 + wcg);
            wv1 = *(const float4*)(W + (size_t)(k0 + wrow) * DM + n0 + wcg + 4);
        }

        const uint32_t as_b = (cur ? as_base1 : as_base0) + a_lane;
        #pragma unroll
        for (int kk = 0; kk < 16; kk += 8) {
            uint32_t a[4][4], b[4][2];
            #pragma unroll
            for (int mi = 0; mi < 4; mi++)
                ldsm4(a[mi], as_b + (uint32_t)((mi * 16 * 20 + kk) * 4));
            #pragma unroll
            for (int ni = 0; ni < 4; ni++) {
                int c = wn * 32 + ni * 8 + g;
                b[ni][0] = Ws[cur][kk + tg][c];
                b[ni][1] = Ws[cur][kk + tg + 4][c];
            }
            #pragma unroll
            for (int mi = 0; mi < 4; mi++)
                #pragma unroll
                for (int ni = 0; ni < 4; ni++)
                    mma8(acc[mi][ni], a[mi], b[ni]);
        }

        if (it + 1 < DM / 16) {
            *(uint4*)&As[nxt][xrow][xcg] =
                make_uint4(f2tf32(xv0.x), f2tf32(xv0.y), f2tf32(xv0.z), f2tf32(xv0.w));
            *(uint4*)&As[nxt][xrow][xcg + 4] =
                make_uint4(f2tf32(xv1.x), f2tf32(xv1.y), f2tf32(xv1.z), f2tf32(xv1.w));
            *(uint4*)&Ws[nxt][wrow][wcg] =
                make_uint4(f2tf32(wv0.x), f2tf32(wv0.y), f2tf32(wv0.z), f2tf32(wv0.w));
            *(uint4*)&Ws[nxt][wrow][wcg + 4] =
                make_uint4(f2tf32(wv1.x), f2tf32(wv1.y), f2tf32(wv1.z), f2tf32(wv1.w));
            __syncthreads();
        }
    }

    const int h = (n0 + wn * 32) >> 6;
    #pragma unroll
    for (int ni = 0; ni < 4; ni++) {
        int gcol = n0 + wn * 32 + ni * 8 + 2 * tg;
        int d    = gcol & 63;
        float b0 = bias[gcol], b1 = bias[gcol + 1];
        #pragma unroll
        for (int mi = 0; mi < 4; mi++) {
            int r0 = m0 + wm * 64 + mi * 16 + g;
            int r1 = r0 + 8;
            int b_0 = r0 >> 11, s0 = r0 & (SS - 1);
            int b_1 = r1 >> 11, s1 = r1 & (SS - 1);
            *(float2*)(outp + (((size_t)(b_0 * HH + h) * SS + s0) * DK) + d) =
                make_float2(acc[mi][ni][0] + b0, acc[mi][ni][1] + b1);
            *(float2*)(outp + (((size_t)(b_1 * HH + h) * SS + s1) * DK) + d) =
                make_float2(acc[mi][ni][2] + b0, acc[mi][ni][3] + b1);
        }
    }
}

// ===========================================================================
// Flash attention v3: 128 threads, 4 warps x 32q band, BK=64 key tiles.
// Q fragments live in registers (extracted once); Q smem region reused as P.
// ===========================================================================
#define KLD 68
#define PLD2 68
#define SMK_B  0
#define SMVT_B (64*KLD*4)                  // 17408
#define SMP_B  (SMVT_B + 64*KLD*4)         // 34816
#define ATTN_SMEM (SMP_B + 128*PLD2*4)     // 69632

__global__ __launch_bounds__(128, 2) void attn_tc(float* __restrict__ out)
{
    extern __shared__ char smem[];
    const uint32_t sb = smem_u32(smem);
    uint32_t* Ks = (uint32_t*)(smem + SMK_B);    // [key][d] 64x68
    uint32_t* Vt = (uint32_t*)(smem + SMVT_B);   // [d][key] 64x68
    uint32_t* Ps = (uint32_t*)(smem + SMP_B);    // [q][key] 128x68 (Q at prologue)

    const int t    = threadIdx.x;
    const int wid  = t >> 5;
    const int lane = t & 31;
    const int g    = lane >> 2;
    const int tg   = lane & 3;
    const int bh   = blockIdx.y;
    const int q0   = blockIdx.x * 128;

    const float* Qp = g_q + ((size_t)bh * SS + q0) * DK;
    const float* Kp = g_k + (size_t)bh * SS * DK;
    const float* Vp = g_v + (size_t)bh * SS * DK;

    // ---- prologue: Q -> (P region) smem, scaled 1/8, tf32 ----
    {
        const float* qp = Qp + (size_t)t * DK;
        #pragma unroll
        for (int c = 0; c < 16; c++) {
            float4 v = *(const float4*)(qp + c * 4);
            *(uint4*)&Ps[t * PLD2 + c * 4] =
                make_uint4(f2tf32(v.x * 0.125f), f2tf32(v.y * 0.125f),
                           f2tf32(v.z * 0.125f), f2tf32(v.w * 0.125f));
        }
    }
    __syncthreads();

    // ldmatrix lane-static pieces
    const int lane15  = lane & 15;
    const int lane7   = lane & 7;
    const int laneHi  = (lane >> 4) & 1;
    const int laneMid = (lane >> 3) & 1;
    const int arow0   = wid * 32;

    // ---- extract Q fragments: qf[mt][k-step][4] ----
    uint32_t qf[2][8][4];
    #pragma unroll
    for (int mt = 0; mt < 2; mt++) {
        uint32_t qa = sb + SMP_B +
            (uint32_t)(((arow0 + mt * 16 + lane15) * PLD2 + laneHi * 4) * 4);
        #pragma unroll
        for (int k0 = 0; k0 < 8; k0++)
            ldsm4(qf[mt][k0], qa + (uint32_t)(k0 * 8 * 4));
    }

    const uint32_t ka = sb + SMK_B +
        (uint32_t)(((laneHi * 8 + lane7) * KLD + laneMid * 4) * 4);
    const uint32_t va = sb + SMVT_B +
        (uint32_t)(((laneHi * 8 + lane7) * KLD + laneMid * 4) * 4);
    const uint32_t pa0 = sb + SMP_B +
        (uint32_t)(((arow0 + lane15) * PLD2 + laneHi * 4) * 4);
    const uint32_t pa1 = pa0 + (uint32_t)(16 * PLD2 * 4);

    float cacc[2][8][4] = {};
    float rs[2][2] = {};

    const int kkey  = t >> 1;          // K loader: key row, half (t&1)
    const int kchal = (t & 1) * 32;
    const int vkey  = t & 63;          // V loader: key row, half (t>>6)
    const int vdhal = (t >> 6) * 32;

    for (int kt = 0; kt < SS / 64; kt++) {
        // ---- load K tile + V tile (transposed) ----
        const float* kp = Kp + (size_t)(kt * 64 + kkey) * DK + kchal;
        const float* vp = Vp + (size_t)(kt * 64 + vkey) * DK + vdhal;
        float4 kv[8], vv[8];
        #pragma unroll
        for (int c = 0; c < 8; c++) {
            kv[c] = *(const float4*)(kp + c * 4);
            vv[c] = *(const float4*)(vp + c * 4);
        }
        __syncthreads();
        #pragma unroll
        for (int c = 0; c < 8; c++) {
            *(uint4*)&Ks[kkey * KLD + kchal + c * 4] =
                make_uint4(f2tf32(kv[c].x), f2tf32(kv[c].y),
                           f2tf32(kv[c].z), f2tf32(kv[c].w));
            int d = vdhal + c * 4;
            Vt[(d + 0) * KLD + vkey] = f2tf32(vv[c].x);
            Vt[(d + 1) * KLD + vkey] = f2tf32(vv[c].y);
            Vt[(d + 2) * KLD + vkey] = f2tf32(vv[c].z);
            Vt[(d + 3) * KLD + vkey] = f2tf32(vv[c].w);
        }
        __syncthreads();

        // ---- S = (Q/8) K^T : 32q x 64k per warp ----
        float sc[2][8][4] = {};
        #pragma unroll
        for (int k0 = 0; k0 < 8; k0++) {
            #pragma unroll
            for (int ni = 0; ni < 8; ni += 2) {
                uint32_t b[4];
                ldsm4(b, ka + (uint32_t)((ni * 8 * KLD + k0 * 8) * 4));
                mma8(sc[0][ni],     qf[0][k0], b);
                mma8(sc[0][ni + 1], qf[0][k0], b + 2);
                mma8(sc[1][ni],     qf[1][k0], b);
                mma8(sc[1][ni + 1], qf[1][k0], b + 2);
            }
        }

        // ---- P = exp(S) -> Ps; rowsum partials ----
        #pragma unroll
        for (int mt = 0; mt < 2; mt++) {
            const int prow = arow0 + mt * 16 + g;
            #pragma unroll
            for (int ni = 0; ni < 8; ni++) {
                float e0 = __expf(sc[mt][ni][0]);
                float e1 = __expf(sc[mt][ni][1]);
                float e2 = __expf(sc[mt][ni][2]);
                float e3 = __expf(sc[mt][ni][3]);
                rs[mt][0] += e0 + e1;
                rs[mt][1] += e2 + e3;
                int col = ni * 8 + 2 * tg;
                *(uint2*)&Ps[prow * PLD2 + col] =
                    make_uint2(f2tf32(e0), f2tf32(e1));
                *(uint2*)&Ps[(prow + 8) * PLD2 + col] =
                    make_uint2(f2tf32(e2), f2tf32(e3));
            }
        }
        __syncwarp();   // P band is per-warp private

        // ---- ctx += P V : 32q x 64d per warp ----
        #pragma unroll
        for (int k0 = 0; k0 < 8; k0++) {
            uint32_t a0[4], a1[4];
            ldsm4(a0, pa0 + (uint32_t)(k0 * 8 * 4));
            ldsm4(a1, pa1 + (uint32_t)(k0 * 8 * 4));
            #pragma unroll
            for (int ni = 0; ni < 8; ni += 2) {
                uint32_t b[4];
                ldsm4(b, va + (uint32_t)((ni * 8 * KLD + k0 * 8) * 4));
                mma8(cacc[0][ni],     a0, b);
                mma8(cacc[0][ni + 1], a0, b + 2);
                mma8(cacc[1][ni],     a1, b);
                mma8(cacc[1][ni + 1], a1, b + 2);
            }
        }
    }

    // ---- rowsum quad-reduce, normalize, store ----
    #pragma unroll
    for (int mt = 0; mt < 2; mt++) {
        rs[mt][0] += __shfl_xor_sync(0xFFFFFFFF, rs[mt][0], 1);
        rs[mt][0] += __shfl_xor_sync(0xFFFFFFFF, rs[mt][0], 2);
        rs[mt][1] += __shfl_xor_sync(0xFFFFFFFF, rs[mt][1], 1);
        rs[mt][1] += __shfl_xor_sync(0xFFFFFFFF, rs[mt][1], 2);
    }

    const int b_ = bh / HH;
    const int h  = bh % HH;
    #pragma unroll
    for (int mt = 0; mt < 2; mt++) {
        const float inv0 = 1.f / (rs[mt][0] + 1e-8f);
        const float inv1 = 1.f / (rs[mt][1] + 1e-8f);
        const int r0 = q0 + arow0 + mt * 16 + g;
        const int r1 = r0 + 8;
        float* o0 = out + (size_t)(b_ * SS + r0) * DM + h * DK;
        float* o1 = out + (size_t)(b_ * SS + r1) * DM + h * DK;
        #pragma unroll
        for (int ni = 0; ni < 8; ni++) {
            int d = ni * 8 + 2 * tg;
            *(float2*)(o0 + d) =
                make_float2(cacc[mt][ni][0] * inv0, cacc[mt][ni][1] * inv0);
            *(float2*)(o1 + d) =
                make_float2(cacc[mt][ni][2] * inv1, cacc[mt][ni][3] * inv1);
        }
    }
}

// ===========================================================================
extern "C" void kernel_launch(void* const* d_in, const int* in_sizes, int n_in,
                              void* d_out, int out_size)
{
    const float* x  = (const float*)d_in[0];
    const float* Wq = (const float*)d_in[1];
    const float* bq = (const float*)d_in[2];
    const float* Wk = (const float*)d_in[3];
    const float* bk = (const float*)d_in[4];
    const float* Wv = (const float*)d_in[5];
    const float* bv = (const float*)d_in[6];
    float* out = (float*)d_out;

    cudaFuncSetAttribute(attn_tc,
                         cudaFuncAttributeMaxDynamicSharedMemorySize, ATTN_SMEM);

    dim3 ggrid(DM / 128, MTOT / 128);   // (8, 32)
    qkv_gemm_tc<<<ggrid, 256>>>(x, Wq, bq, 0);
    qkv_gemm_tc<<<ggrid, 256>>>(x, Wk, bk, 1);
    qkv_gemm_tc<<<ggrid, 256>>>(x, Wv, bv, 2);

    dim3 agrid(SS / 128, BB * HH);      // (16, 32)
    attn_tc<<<agrid, 128, ATTN_SMEM>>>(out);
}

// round 7
// speedup vs baseline: 3.4091x; 1.1092x over previous
#include <cuda_runtime.h>
#include <cstdint>

#define BB   2
#define SS   2048
#define HH   16
#define DK   64
#define DM   1024
#define MTOT (BB*SS)   // 4096

__device__ float g_q[BB*HH*SS*DK];
__device__ float g_k[BB*HH*SS*DK];
__device__ float g_v[BB*HH*SS*DK];

// ---------------------------------------------------------------------------
__device__ __forceinline__ uint32_t f2tf32(float f) {
    uint32_t r;
    asm("cvt.rna.tf32.f32 %0, %1;" : "=r"(r) : "f"(f));
    return r;
}
__device__ __forceinline__ uint32_t smem_u32(const void* p) {
    uint32_t a;
    asm("{ .reg .u64 t; cvta.to.shared.u64 t, %1; cvt.u32.u64 %0, t; }"
        : "=r"(a) : "l"(p));
    return a;
}
__device__ __forceinline__ void mma8(float c[4], const uint32_t* a,
                                     const uint32_t* b) {
    asm volatile(
        "mma.sync.aligned.m16n8k8.row.col.f32.tf32.tf32.f32 "
        "{%0,%1,%2,%3}, {%4,%5,%6,%7}, {%8,%9}, {%0,%1,%2,%3};"
        : "+f"(c[0]), "+f"(c[1]), "+f"(c[2]), "+f"(c[3])
        : "r"(a[0]), "r"(a[1]), "r"(a[2]), "r"(a[3]), "r"(b[0]), "r"(b[1]));
}
__device__ __forceinline__ void ldsm4(uint32_t r[4], uint32_t addr) {
    asm volatile("ldmatrix.sync.aligned.m8n8.x4.shared.b16 {%0,%1,%2,%3}, [%4];"
                 : "=r"(r[0]), "=r"(r[1]), "=r"(r[2]), "=r"(r[3]) : "r"(addr));
}

// ===========================================================================
// QKV GEMM, fused over z: CTA 128x128, 8 warps, double-buffered + ldmatrix
// ===========================================================================
__global__ __launch_bounds__(256, 2) void qkv_gemm_tc(
    const float* __restrict__ x,
    const float* __restrict__ Wq, const float* __restrict__ bq,
    const float* __restrict__ Wk, const float* __restrict__ bk,
    const float* __restrict__ Wv, const float* __restrict__ bv)
{
    __shared__ uint32_t As[2][128][20];
    __shared__ uint32_t Ws[2][16][132];

    const int sel = blockIdx.z;
    const float* W    = (sel == 0) ? Wq : (sel == 1) ? Wk : Wv;
    const float* bias = (sel == 0) ? bq : (sel == 1) ? bk : bv;
    float* outp       = (sel == 0) ? g_q : (sel == 1) ? g_k : g_v;

    const int t    = threadIdx.x;
    const int wid  = t >> 5;
    const int lane = t & 31;
    const int g    = lane >> 2;
    const int tg   = lane & 3;
    const int wm   = wid & 1;
    const int wn   = wid >> 1;
    const int m0   = blockIdx.y * 128;
    const int n0   = blockIdx.x * 128;

    const int xrow = t >> 1, xcg = (t & 1) * 8;
    const int wrow = t >> 4, wcg = (t & 15) * 8;

    const int lane15  = lane & 15;
    const int laneHi4 = ((lane >> 4) & 1) * 4;
    const uint32_t as_base0 = smem_u32(&As[0][0][0]);
    const uint32_t as_base1 = smem_u32(&As[1][0][0]);
    const uint32_t a_lane   = (uint32_t)(((wm * 64 + lane15) * 20 + laneHi4) * 4);

    float acc[4][4][4] = {};
    float4 xv0, xv1, wv0, wv1;

    xv0 = *(const float4*)(x + (size_t)(m0 + xrow) * DM + xcg);
    xv1 = *(const float4*)(x + (size_t)(m0 + xrow) * DM + xcg + 4);
    wv0 = *(const float4*)(W + (size_t)wrow * DM + n0 + wcg);
    wv1 = *(const float4*)(W + (size_t)wrow * DM + n0 + wcg + 4);
    *(uint4*)&As[0][xrow][xcg] =
        make_uint4(f2tf32(xv0.x), f2tf32(xv0.y), f2tf32(xv0.z), f2tf32(xv0.w));
    *(uint4*)&As[0][xrow][xcg + 4] =
        make_uint4(f2tf32(xv1.x), f2tf32(xv1.y), f2tf32(xv1.z), f2tf32(xv1.w));
    *(uint4*)&Ws[0][wrow][wcg] =
        make_uint4(f2tf32(wv0.x), f2tf32(wv0.y), f2tf32(wv0.z), f2tf32(wv0.w));
    *(uint4*)&Ws[0][wrow][wcg + 4] =
        make_uint4(f2tf32(wv1.x), f2tf32(wv1.y), f2tf32(wv1.z), f2tf32(wv1.w));
    __syncthreads();

    for (int it = 0; it < DM / 16; it++) {
        const int cur = it & 1;
        const int nxt = cur ^ 1;
        if (it + 1 < DM / 16) {
            int k0 = (it + 1) * 16;
            xv0 = *(const float4*)(x + (size_t)(m0 + xrow) * DM + k0 + xcg);
            xv1 = *(const float4*)(x + (size_t)(m0 + xrow) * DM + k0 + xcg + 4);
            wv0 = *(const float4*)(W + (size_t)(k0 + wrow) * DM + n0 + wcg);
            wv1 = *(const float4*)(W + (size_t)(k0 + wrow) * DM + n0 + wcg + 4);
        }

        const uint32_t as_b = (cur ? as_base1 : as_base0) + a_lane;
        #pragma unroll
        for (int kk = 0; kk < 16; kk += 8) {
            uint32_t a[4][4], b[4][2];
            #pragma unroll
            for (int mi = 0; mi < 4; mi++)
                ldsm4(a[mi], as_b + (uint32_t)((mi * 16 * 20 + kk) * 4));
            #pragma unroll
            for (int ni = 0; ni < 4; ni++) {
                int c = wn * 32 + ni * 8 + g;
                b[ni][0] = Ws[cur][kk + tg][c];
                b[ni][1] = Ws[cur][kk + tg + 4][c];
            }
            #pragma unroll
            for (int mi = 0; mi < 4; mi++)
                #pragma unroll
                for (int ni = 0; ni < 4; ni++)
                    mma8(acc[mi][ni], a[mi], b[ni]);
        }

        if (it + 1 < DM / 16) {
            *(uint4*)&As[nxt][xrow][xcg] =
                make_uint4(f2tf32(xv0.x), f2tf32(xv0.y), f2tf32(xv0.z), f2tf32(xv0.w));
            *(uint4*)&As[nxt][xrow][xcg + 4] =
                make_uint4(f2tf32(xv1.x), f2tf32(xv1.y), f2tf32(xv1.z), f2tf32(xv1.w));
            *(uint4*)&Ws[nxt][wrow][wcg] =
                make_uint4(f2tf32(wv0.x), f2tf32(wv0.y), f2tf32(wv0.z), f2tf32(wv0.w));
            *(uint4*)&Ws[nxt][wrow][wcg + 4] =
                make_uint4(f2tf32(wv1.x), f2tf32(wv1.y), f2tf32(wv1.z), f2tf32(wv1.w));
            __syncthreads();
        }
    }

    const int h = (n0 + wn * 32) >> 6;
    #pragma unroll
    for (int ni = 0; ni < 4; ni++) {
        int gcol = n0 + wn * 32 + ni * 8 + 2 * tg;
        int d    = gcol & 63;
        float b0 = bias[gcol], b1 = bias[gcol + 1];
        #pragma unroll
        for (int mi = 0; mi < 4; mi++) {
            int r0 = m0 + wm * 64 + mi * 16 + g;
            int r1 = r0 + 8;
            int b_0 = r0 >> 11, s0 = r0 & (SS - 1);
            int b_1 = r1 >> 11, s1 = r1 & (SS - 1);
            *(float2*)(outp + (((size_t)(b_0 * HH + h) * SS + s0) * DK) + d) =
                make_float2(acc[mi][ni][0] + b0, acc[mi][ni][1] + b1);
            *(float2*)(outp + (((size_t)(b_1 * HH + h) * SS + s1) * DK) + d) =
                make_float2(acc[mi][ni][2] + b0, acc[mi][ni][3] + b1);
        }
    }
}

// ===========================================================================
// Flash attention v4: P never touches SMEM.
// S C-frags are reused directly as PV A-frags; V is stored with its key rows
// permuted within 8-groups (k -> (k>>1)+(k&1)*4) so the sum is unchanged.
// 128 threads, 4 warps x 32q, BK=64. SMEM = K tile + permuted Vt only (34KB).
// ===========================================================================
#define KLD 68

__global__ __launch_bounds__(128, 2) void attn_tc(float* __restrict__ out)
{
    __shared__ uint32_t smK[64 * KLD];   // [key][d] 64x68 (Q staging lower half)
    __shared__ uint32_t smV[64 * KLD];   // [d][key-perm] 64x68 (Q staging upper)

    const int t    = threadIdx.x;
    const int wid  = t >> 5;
    const int lane = t & 31;
    const int g    = lane >> 2;
    const int tg   = lane & 3;
    const int bh   = blockIdx.y;
    const int q0   = blockIdx.x * 128;

    const float* Qp = g_q + ((size_t)bh * SS + q0) * DK;
    const float* Kp = g_k + (size_t)bh * SS * DK;
    const float* Vp = g_v + (size_t)bh * SS * DK;

    // ---- prologue: stage Q (rows 0-63 -> smK, 64-127 -> smV), tf32, /8 ----
    {
        uint32_t* Qst = (t < 64) ? &smK[t * KLD] : &smV[(t - 64) * KLD];
        const float* qp = Qp + (size_t)t * DK;
        #pragma unroll
        for (int c = 0; c < 16; c++) {
            float4 v = *(const float4*)(qp + c * 4);
            *(uint4*)&Qst[c * 4] =
                make_uint4(f2tf32(v.x * 0.125f), f2tf32(v.y * 0.125f),
                           f2tf32(v.z * 0.125f), f2tf32(v.w * 0.125f));
        }
    }
    __syncthreads();

    const int lane15  = lane & 15;
    const int lane7   = lane & 7;
    const int laneHi  = (lane >> 4) & 1;
    const int laneMid = (lane >> 3) & 1;
    const int arow0   = wid * 32;

    // ---- extract Q fragments from staging ----
    uint32_t qf[2][8][4];
    #pragma unroll
    for (int mt = 0; mt < 2; mt++) {
        int qrow = arow0 + mt * 16 + lane15;
        uint32_t qa = (qrow < 64) ? smem_u32(&smK[qrow * KLD])
                                  : smem_u32(&smV[(qrow - 64) * KLD]);
        qa += (uint32_t)(laneHi * 16);
        #pragma unroll
        for (int k0 = 0; k0 < 8; k0++)
            ldsm4(qf[mt][k0], qa + (uint32_t)(k0 * 32));
    }
    __syncthreads();   // all Q frags extracted before K/V overwrite staging

    const uint32_t ka = smem_u32(smK) +
        (uint32_t)(((laneHi * 8 + lane7) * KLD + laneMid * 4) * 4);
    const uint32_t va = smem_u32(smV) +
        (uint32_t)(((laneHi * 8 + lane7) * KLD + laneMid * 4) * 4);

    float cacc[2][8][4] = {};
    float rs[2][2] = {};

    const int kkey  = t >> 1;          // K loader: key row, half (t&1)
    const int kchal = (t & 1) * 32;
    const int vkey  = t & 63;          // V loader: key row, d-half (t>>6)
    const int vdhal = (t >> 6) * 32;
    // permuted key slot within 8-group: k -> (k>>1) + (k&1)*4
    const int vcol  = (vkey & ~7) | ((vkey >> 1) & 3) | ((vkey & 1) << 2);

    for (int kt = 0; kt < SS / 64; kt++) {
        const float* kp = Kp + (size_t)(kt * 64 + kkey) * DK + kchal;
        const float* vp = Vp + (size_t)(kt * 64 + vkey) * DK + vdhal;
        float4 kv[8], vv[8];
        #pragma unroll
        for (int c = 0; c < 8; c++) {
            kv[c] = *(const float4*)(kp + c * 4);
            vv[c] = *(const float4*)(vp + c * 4);
        }
        __syncthreads();   // prev iter's frag reads done
        #pragma unroll
        for (int c = 0; c < 8; c++) {
            *(uint4*)&smK[kkey * KLD + kchal + c * 4] =
                make_uint4(f2tf32(kv[c].x), f2tf32(kv[c].y),
                           f2tf32(kv[c].z), f2tf32(kv[c].w));
            int d = vdhal + c * 4;
            smV[(d + 0) * KLD + vcol] = f2tf32(vv[c].x);
            smV[(d + 1) * KLD + vcol] = f2tf32(vv[c].y);
            smV[(d + 2) * KLD + vcol] = f2tf32(vv[c].z);
            smV[(d + 3) * KLD + vcol] = f2tf32(vv[c].w);
        }
        __syncthreads();

        // ---- S = (Q/8) K^T : 32q x 64k per warp ----
        float sc[2][8][4] = {};
        #pragma unroll
        for (int k0 = 0; k0 < 8; k0++) {
            #pragma unroll
            for (int ni = 0; ni < 8; ni += 2) {
                uint32_t b[4];
                ldsm4(b, ka + (uint32_t)((ni * 8 * KLD + k0 * 8) * 4));
                mma8(sc[0][ni],     qf[0][k0], b);
                mma8(sc[0][ni + 1], qf[0][k0], b + 2);
                mma8(sc[1][ni],     qf[1][k0], b);
                mma8(sc[1][ni + 1], qf[1][k0], b + 2);
            }
        }

        // ---- P = exp(S) in registers; C-frag -> A-frag (a = {c0,c2,c1,c3}) ----
        uint32_t pf[2][8][4];
        #pragma unroll
        for (int mt = 0; mt < 2; mt++) {
            #pragma unroll
            for (int ni = 0; ni < 8; ni++) {
                float e0 = __expf(sc[mt][ni][0]);
                float e1 = __expf(sc[mt][ni][1]);
                float e2 = __expf(sc[mt][ni][2]);
                float e3 = __expf(sc[mt][ni][3]);
                rs[mt][0] += e0 + e1;
                rs[mt][1] += e2 + e3;
                pf[mt][ni][0] = f2tf32(e0);
                pf[mt][ni][1] = f2tf32(e2);
                pf[mt][ni][2] = f2tf32(e1);
                pf[mt][ni][3] = f2tf32(e3);
            }
        }

        // ---- ctx += P V (A-frags from registers, V key-permuted) ----
        #pragma unroll
        for (int ni = 0; ni < 8; ni++) {    // ni = PV k-step (8 keys)
            #pragma unroll
            for (int dt = 0; dt < 8; dt += 2) {
                uint32_t b[4];
                ldsm4(b, va + (uint32_t)((dt * 8 * KLD + ni * 8) * 4));
                mma8(cacc[0][dt],     pf[0][ni], b);
                mma8(cacc[0][dt + 1], pf[0][ni], b + 2);
                mma8(cacc[1][dt],     pf[1][ni], b);
                mma8(cacc[1][dt + 1], pf[1][ni], b + 2);
            }
        }
    }

    // ---- rowsum quad-reduce, normalize, store ----
    #pragma unroll
    for (int mt = 0; mt < 2; mt++) {
        rs[mt][0] += __shfl_xor_sync(0xFFFFFFFF, rs[mt][0], 1);
        rs[mt][0] += __shfl_xor_sync(0xFFFFFFFF, rs[mt][0], 2);
        rs[mt][1] += __shfl_xor_sync(0xFFFFFFFF, rs[mt][1], 1);
        rs[mt][1] += __shfl_xor_sync(0xFFFFFFFF, rs[mt][1], 2);
    }

    const int b_ = bh / HH;
    const int h  = bh % HH;
    #pragma unroll
    for (int mt = 0; mt < 2; mt++) {
        const float inv0 = 1.f / (rs[mt][0] + 1e-8f);
        const float inv1 = 1.f / (rs[mt][1] + 1e-8f);
        const int r0 = q0 + arow0 + mt * 16 + g;
        const int r1 = r0 + 8;
        float* o0 = out + (size_t)(b_ * SS + r0) * DM + h * DK;
        float* o1 = out + (size_t)(b_ * SS + r1) * DM + h * DK;
        #pragma unroll
        for (int ni = 0; ni < 8; ni++) {
            int d = ni * 8 + 2 * tg;
            *(float2*)(o0 + d) =
                make_float2(cacc[mt][ni][0] * inv0, cacc[mt][ni][1] * inv0);
            *(float2*)(o1 + d) =
                make_float2(cacc[mt][ni][2] * inv1, cacc[mt][ni][3] * inv1);
        }
    }
}

// ===========================================================================
extern "C" void kernel_launch(void* const* d_in, const int* in_sizes, int n_in,
                              void* d_out, int out_size)
{
    const float* x  = (const float*)d_in[0];
    const float* Wq = (const float*)d_in[1];
    const float* bq = (const float*)d_in[2];
    const float* Wk = (const float*)d_in[3];
    const float* bk = (const float*)d_in[4];
    const float* Wv = (const float*)d_in[5];
    const float* bv = (const float*)d_in[6];
    float* out = (float*)d_out;

    dim3 ggrid(DM / 128, MTOT / 128, 3);   // (8, 32, 3)
    qkv_gemm_tc<<<ggrid, 256>>>(x, Wq, bq, Wk, bk, Wv, bv);

    dim3 agrid(SS / 128, BB * HH);         // (16, 32)
    attn_tc<<<agrid, 128>>>(out);
}

// round 10
// speedup vs baseline: 3.4255x; 1.0048x over previous
#include <cuda_runtime.h>
#include <cstdint>

#define BB   2
#define SS   2048
#define HH   16
#define DK   64
#define DM   1024
#define MTOT (BB*SS)   // 4096

// Q/K: tf32 bits, [B,H,S,Dk] (Q pre-scaled by 1/8).
// V:   tf32 bits, [B,H,Dk,S] d-major, with key-permutation baked into s.
__device__ uint32_t g_q[BB*HH*SS*DK];
__device__ uint32_t g_k[BB*HH*SS*DK];
__device__ uint32_t g_v[BB*HH*SS*DK];

// ---------------------------------------------------------------------------
__device__ __forceinline__ uint32_t f2tf32(float f) {
    uint32_t r;
    asm("cvt.rna.tf32.f32 %0, %1;" : "=r"(r) : "f"(f));
    return r;
}
__device__ __forceinline__ uint32_t smem_u32(const void* p) {
    uint32_t a;
    asm("{ .reg .u64 t; cvta.to.shared.u64 t, %1; cvt.u32.u64 %0, t; }"
        : "=r"(a) : "l"(p));
    return a;
}
__device__ __forceinline__ void mma8(float c[4], const uint32_t* a,
                                     const uint32_t* b) {
    asm volatile(
        "mma.sync.aligned.m16n8k8.row.col.f32.tf32.tf32.f32 "
        "{%0,%1,%2,%3}, {%4,%5,%6,%7}, {%8,%9}, {%0,%1,%2,%3};"
        : "+f"(c[0]), "+f"(c[1]), "+f"(c[2]), "+f"(c[3])
        : "r"(a[0]), "r"(a[1]), "r"(a[2]), "r"(a[3]), "r"(b[0]), "r"(b[1]));
}
__device__ __forceinline__ void ldsm4(uint32_t r[4], uint32_t addr) {
    asm volatile("ldmatrix.sync.aligned.m8n8.x4.shared.b16 {%0,%1,%2,%3}, [%4];"
                 : "=r"(r[0]), "=r"(r[1]), "=r"(r[2]), "=r"(r[3]) : "r"(addr));
}
__device__ __forceinline__ void cp16(uint32_t dst, const void* src) {
    asm volatile("cp.async.cg.shared.global [%0], [%1], 16;"
                 :: "r"(dst), "l"(src));
}
#define CP_COMMIT() asm volatile("cp.async.commit_group;" ::: "memory")
#define CP_WAIT0()  asm volatile("cp.async.wait_group 0;" ::: "memory")
#define CP_WAIT1()  asm volatile("cp.async.wait_group 1;" ::: "memory")

// ===========================================================================
// QKV GEMM, fused over z; epilogue converts to tf32 bits (+scale, +V layout)
// ===========================================================================
__global__ __launch_bounds__(256, 2) void qkv_gemm_tc(
    const float* __restrict__ x,
    const float* __restrict__ Wq, const float* __restrict__ bq,
    const float* __restrict__ Wk, const float* __restrict__ bk,
    const float* __restrict__ Wv, const float* __restrict__ bv)
{
    __shared__ uint32_t As[2][128][20];
    __shared__ uint32_t Ws[2][16][132];

    const int sel = blockIdx.z;
    const float* W    = (sel == 0) ? Wq : (sel == 1) ? Wk : Wv;
    const float* bias = (sel == 0) ? bq : (sel == 1) ? bk : bv;

    const int t    = threadIdx.x;
    const int wid  = t >> 5;
    const int lane = t & 31;
    const int g    = lane >> 2;
    const int tg   = lane & 3;
    const int wm   = wid & 1;
    const int wn   = wid >> 1;
    const int m0   = blockIdx.y * 128;
    const int n0   = blockIdx.x * 128;

    const int xrow = t >> 1, xcg = (t & 1) * 8;
    const int wrow = t >> 4, wcg = (t & 15) * 8;

    const int lane15  = lane & 15;
    const int laneHi4 = ((lane >> 4) & 1) * 4;
    const uint32_t as_base0 = smem_u32(&As[0][0][0]);
    const uint32_t as_base1 = smem_u32(&As[1][0][0]);
    const uint32_t a_lane   = (uint32_t)(((wm * 64 + lane15) * 20 + laneHi4) * 4);

    float acc[4][4][4] = {};
    float4 xv0, xv1, wv0, wv1;

    xv0 = *(const float4*)(x + (size_t)(m0 + xrow) * DM + xcg);
    xv1 = *(const float4*)(x + (size_t)(m0 + xrow) * DM + xcg + 4);
    wv0 = *(const float4*)(W + (size_t)wrow * DM + n0 + wcg);
    wv1 = *(const float4*)(W + (size_t)wrow * DM + n0 + wcg + 4);
    *(uint4*)&As[0][xrow][xcg] =
        make_uint4(f2tf32(xv0.x), f2tf32(xv0.y), f2tf32(xv0.z), f2tf32(xv0.w));
    *(uint4*)&As[0][xrow][xcg + 4] =
        make_uint4(f2tf32(xv1.x), f2tf32(xv1.y), f2tf32(xv1.z), f2tf32(xv1.w));
    *(uint4*)&Ws[0][wrow][wcg] =
        make_uint4(f2tf32(wv0.x), f2tf32(wv0.y), f2tf32(wv0.z), f2tf32(wv0.w));
    *(uint4*)&Ws[0][wrow][wcg + 4] =
        make_uint4(f2tf32(wv1.x), f2tf32(wv1.y), f2tf32(wv1.z), f2tf32(wv1.w));
    __syncthreads();

    for (int it = 0; it < DM / 16; it++) {
        const int cur = it & 1;
        const int nxt = cur ^ 1;
        if (it + 1 < DM / 16) {
            int k0 = (it + 1) * 16;
            xv0 = *(const float4*)(x + (size_t)(m0 + xrow) * DM + k0 + xcg);
            xv1 = *(const float4*)(x + (size_t)(m0 + xrow) * DM + k0 + xcg + 4);
            wv0 = *(const float4*)(W + (size_t)(k0 + wrow) * DM + n0 + wcg);
            wv1 = *(const float4*)(W + (size_t)(k0 + wrow) * DM + n0 + wcg + 4);
        }

        const uint32_t as_b = (cur ? as_base1 : as_base0) + a_lane;
        #pragma unroll
        for (int kk = 0; kk < 16; kk += 8) {
            uint32_t a[4][4], b[4][2];
            #pragma unroll
            for (int mi = 0; mi < 4; mi++)
                ldsm4(a[mi], as_b + (uint32_t)((mi * 16 * 20 + kk) * 4));
            #pragma unroll
            for (int ni = 0; ni < 4; ni++) {
                int c = wn * 32 + ni * 8 + g;
                b[ni][0] = Ws[cur][kk + tg][c];
                b[ni][1] = Ws[cur][kk + tg + 4][c];
            }
            #pragma unroll
            for (int mi = 0; mi < 4; mi++)
                #pragma unroll
                for (int ni = 0; ni < 4; ni++)
                    mma8(acc[mi][ni], a[mi], b[ni]);
        }

        if (it + 1 < DM / 16) {
            *(uint4*)&As[nxt][xrow][xcg] =
                make_uint4(f2tf32(xv0.x), f2tf32(xv0.y), f2tf32(xv0.z), f2tf32(xv0.w));
            *(uint4*)&As[nxt][xrow][xcg + 4] =
                make_uint4(f2tf32(xv1.x), f2tf32(xv1.y), f2tf32(xv1.z), f2tf32(xv1.w));
            *(uint4*)&Ws[nxt][wrow][wcg] =
                make_uint4(f2tf32(wv0.x), f2tf32(wv0.y), f2tf32(wv0.z), f2tf32(wv0.w));
            *(uint4*)&Ws[nxt][wrow][wcg + 4] =
                make_uint4(f2tf32(wv1.x), f2tf32(wv1.y), f2tf32(wv1.z), f2tf32(wv1.w));
            __syncthreads();
        }
    }

    // ---- epilogue: +bias, convert tf32, scatter per-destination layout ----
    const int h = (n0 + wn * 32) >> 6;
    #pragma unroll
    for (int ni = 0; ni < 4; ni++) {
        int gcol = n0 + wn * 32 + ni * 8 + 2 * tg;
        int d    = gcol & 63;
        float b0 = bias[gcol], b1 = bias[gcol + 1];
        #pragma unroll
        for (int mi = 0; mi < 4; mi++) {
            int r0 = m0 + wm * 64 + mi * 16 + g;
            int r1 = r0 + 8;
            int b_0 = r0 >> 11, s0 = r0 & (SS - 1);
            int b_1 = r1 >> 11, s1 = r1 & (SS - 1);
            float v00 = acc[mi][ni][0] + b0, v01 = acc[mi][ni][1] + b1;
            float v10 = acc[mi][ni][2] + b0, v11 = acc[mi][ni][3] + b1;
            if (sel == 0) {          // Q: pre-scale by 1/8
                uint32_t* p0 = g_q + (((size_t)(b_0 * HH + h) * SS + s0) * DK) + d;
                uint32_t* p1 = g_q + (((size_t)(b_1 * HH + h) * SS + s1) * DK) + d;
                *(uint2*)p0 = make_uint2(f2tf32(v00 * 0.125f), f2tf32(v01 * 0.125f));
                *(uint2*)p1 = make_uint2(f2tf32(v10 * 0.125f), f2tf32(v11 * 0.125f));
            } else if (sel == 1) {   // K
                uint32_t* p0 = g_k + (((size_t)(b_0 * HH + h) * SS + s0) * DK) + d;
                uint32_t* p1 = g_k + (((size_t)(b_1 * HH + h) * SS + s1) * DK) + d;
                *(uint2*)p0 = make_uint2(f2tf32(v00), f2tf32(v01));
                *(uint2*)p1 = make_uint2(f2tf32(v10), f2tf32(v11));
            } else {                 // V: [B,H,Dk,S], s permuted within 8-group
                int s0p = (s0 & ~7) | ((s0 >> 1) & 3) | ((s0 & 1) << 2);
                int s1p = (s1 & ~7) | ((s1 >> 1) & 3) | ((s1 & 1) << 2);
                uint32_t* vb = g_v + ((size_t)(b_0 * HH + h) * DK + d) * SS;
                vb[s0p]        = f2tf32(v00);
                vb[SS + s0p]   = f2tf32(v01);
                uint32_t* vb1 = g_v + ((size_t)(b_1 * HH + h) * DK + d) * SS;
                vb1[s1p]       = f2tf32(v10);
                vb1[SS + s1p]  = f2tf32(v11);
            }
        }
    }
}

// ===========================================================================
// Flash attention v5 (loader stride fixed): cp.async double-buffered K/Vt,
// zero in-kernel conversion. 128 threads, 4 warps x 32q, BK=64.
// ===========================================================================
#define KLD   68
#define BUFW  (64 * KLD)               // words per K (or V) tile buffer
#define ATTN_SMEM (4 * BUFW * 4)       // K0 V0 K1 V1 = 69632 B

__global__ __launch_bounds__(128, 2) void attn_tc(float* __restrict__ out)
{
    extern __shared__ uint32_t sm[];   // [K0][V0][K1][V1]
    const uint32_t sb = smem_u32(sm);

    const int t    = threadIdx.x;
    const int wid  = t >> 5;
    const int lane = t & 31;
    const int g    = lane >> 2;
    const int tg   = lane & 3;
    const int bh   = blockIdx.y;
    const int q0   = blockIdx.x * 128;

    const uint32_t* Qp = g_q + ((size_t)bh * SS + q0) * DK;
    const uint32_t* Kp = g_k + (size_t)bh * SS * DK;
    const uint32_t* Vp = g_v + (size_t)bh * DK * SS;   // d-major, perm baked

    // ---- prologue: stage full Q tile (128 rows x 64 words) via cp.async ----
    #pragma unroll
    for (int c = 0; c < 16; c++)
        cp16(sb + (uint32_t)((t * KLD + c * 4) * 4), Qp + (size_t)t * DK + c * 4);
    CP_COMMIT();
    CP_WAIT0();
    __syncthreads();

    const int lane15  = lane & 15;
    const int lane7   = lane & 7;
    const int laneHi  = (lane >> 4) & 1;
    const int laneMid = (lane >> 3) & 1;
    const int arow0   = wid * 32;

    // ---- extract Q fragments ----
    uint32_t qf[2][8][4];
    #pragma unroll
    for (int mt = 0; mt < 2; mt++) {
        uint32_t qa = sb +
            (uint32_t)(((arow0 + mt * 16 + lane15) * KLD + laneHi * 4) * 4);
        #pragma unroll
        for (int k0 = 0; k0 < 8; k0++)
            ldsm4(qf[mt][k0], qa + (uint32_t)(k0 * 32));
    }
    __syncthreads();   // Q frags extracted before tile0 overwrites buf0

    // loader mapping: thread t -> row t>>1, col-half (t&1)*32 (32 words each)
    const int lrow = t >> 1;
    const int lcol = (t & 1) * 32;
    const uint32_t kdst = sb + (uint32_t)((lrow * KLD + lcol) * 4);
    const uint32_t vdst = kdst + (uint32_t)(BUFW * 4);

    const uint32_t ka = sb +
        (uint32_t)(((laneHi * 8 + lane7) * KLD + laneMid * 4) * 4);
    const uint32_t va = ka + (uint32_t)(BUFW * 4);

    float cacc[2][8][4] = {};
    float rs[2][2] = {};

    // issue tile 0 -> buf0 (8 x 16B chunks each for K and V; dst stride 16B)
    {
        const uint32_t* ks = Kp + (size_t)lrow * DK + lcol;
        const uint32_t* vs = Vp + (size_t)lrow * SS + lcol;
        #pragma unroll
        for (int c = 0; c < 8; c++) {
            cp16(kdst + (uint32_t)(c * 16), ks + c * 4);
            cp16(vdst + (uint32_t)(c * 16), vs + c * 4);
        }
        CP_COMMIT();
    }

    for (int kt = 0; kt < SS / 64; kt++) {
        const int cur = kt & 1;
        if (kt > 0) __syncthreads();   // all warps done with buf[cur^1]
        if (kt + 1 < SS / 64) {
            const uint32_t boff = (uint32_t)((cur ^ 1) * 2 * BUFW * 4);
            const uint32_t* ks = Kp + (size_t)((kt + 1) * 64 + lrow) * DK + lcol;
            const uint32_t* vs = Vp + (size_t)lrow * SS + (kt + 1) * 64 + lcol;
            #pragma unroll
            for (int c = 0; c < 8; c++) {
                cp16(kdst + boff + (uint32_t)(c * 16), ks + c * 4);
                cp16(vdst + boff + (uint32_t)(c * 16), vs + c * 4);
            }
            CP_COMMIT();
            CP_WAIT1();                // tile kt's group complete (this thread)
        } else {
            CP_WAIT0();
        }
        __syncthreads();               // whole tile kt visible

        const uint32_t cb  = (uint32_t)(cur * 2 * BUFW * 4);
        const uint32_t kac = ka + cb;
        const uint32_t vac = va + cb;

        // ---- S = (Q/8) K^T : 32q x 64k per warp ----
        float sc[2][8][4] = {};
        #pragma unroll
        for (int k0 = 0; k0 < 8; k0++) {
            #pragma unroll
            for (int ni = 0; ni < 8; ni += 2) {
                uint32_t b[4];
                ldsm4(b, kac + (uint32_t)((ni * 8 * KLD + k0 * 8) * 4));
                mma8(sc[0][ni],     qf[0][k0], b);
                mma8(sc[0][ni + 1], qf[0][k0], b + 2);
                mma8(sc[1][ni],     qf[1][k0], b);
                mma8(sc[1][ni + 1], qf[1][k0], b + 2);
            }
        }

        // ---- P = exp(S) in registers; C-frag -> A-frag ({c0,c2,c1,c3}) ----
        uint32_t pf[2][8][4];
        #pragma unroll
        for (int mt = 0; mt < 2; mt++) {
            #pragma unroll
            for (int ni = 0; ni < 8; ni++) {
                float e0 = __expf(sc[mt][ni][0]);
                float e1 = __expf(sc[mt][ni][1]);
                float e2 = __expf(sc[mt][ni][2]);
                float e3 = __expf(sc[mt][ni][3]);
                rs[mt][0] += e0 + e1;
                rs[mt][1] += e2 + e3;
                pf[mt][ni][0] = f2tf32(e0);
                pf[mt][ni][1] = f2tf32(e2);
                pf[mt][ni][2] = f2tf32(e1);
                pf[mt][ni][3] = f2tf32(e3);
            }
        }

        // ---- ctx += P V (A-frags from registers, V key-permuted in gmem) ----
        #pragma unroll
        for (int ni = 0; ni < 8; ni++) {
            #pragma unroll
            for (int dt = 0; dt < 8; dt += 2) {
                uint32_t b[4];
                ldsm4(b, vac + (uint32_t)((dt * 8 * KLD + ni * 8) * 4));
                mma8(cacc[0][dt],     pf[0][ni], b);
                mma8(cacc[0][dt + 1], pf[0][ni], b + 2);
                mma8(cacc[1][dt],     pf[1][ni], b);
                mma8(cacc[1][dt + 1], pf[1][ni], b + 2);
            }
        }
    }

    // ---- rowsum quad-reduce, normalize, store ----
    #pragma unroll
    for (int mt = 0; mt < 2; mt++) {
        rs[mt][0] += __shfl_xor_sync(0xFFFFFFFF, rs[mt][0], 1);
        rs[mt][0] += __shfl_xor_sync(0xFFFFFFFF, rs[mt][0], 2);
        rs[mt][1] += __shfl_xor_sync(0xFFFFFFFF, rs[mt][1], 1);
        rs[mt][1] += __shfl_xor_sync(0xFFFFFFFF, rs[mt][1], 2);
    }

    const int b_ = bh / HH;
    const int h  = bh % HH;
    #pragma unroll
    for (int mt = 0; mt < 2; mt++) {
        const float inv0 = 1.f / (rs[mt][0] + 1e-8f);
        const float inv1 = 1.f / (rs[mt][1] + 1e-8f);
        const int r0 = q0 + arow0 + mt * 16 + g;
        const int r1 = r0 + 8;
        float* o0 = out + (size_t)(b_ * SS + r0) * DM + h * DK;
        float* o1 = out + (size_t)(b_ * SS + r1) * DM + h * DK;
        #pragma unroll
        for (int ni = 0; ni < 8; ni++) {
            int d = ni * 8 + 2 * tg;
            *(float2*)(o0 + d) =
                make_float2(cacc[mt][ni][0] * inv0, cacc[mt][ni][1] * inv0);
            *(float2*)(o1 + d) =
                make_float2(cacc[mt][ni][2] * inv1, cacc[mt][ni][3] * inv1);
        }
    }
}

// ===========================================================================
extern "C" void kernel_launch(void* const* d_in, const int* in_sizes, int n_in,
                              void* d_out, int out_size)
{
    const float* x  = (const float*)d_in[0];
    const float* Wq = (const float*)d_in[1];
    const float* bq = (const float*)d_in[2];
    const float* Wk = (const float*)d_in[3];
    const float* bk = (const float*)d_in[4];
    const float* Wv = (const float*)d_in[5];
    const float* bv = (const float*)d_in[6];
    float* out = (float*)d_out;

    cudaFuncSetAttribute(attn_tc,
                         cudaFuncAttributeMaxDynamicSharedMemorySize, ATTN_SMEM);

    dim3 ggrid(DM / 128, MTOT / 128, 3);   // (8, 32, 3)
    qkv_gemm_tc<<<ggrid, 256>>>(x, Wq, bq, Wk, bk, Wv, bv);

    dim3 agrid(SS / 128, BB * HH);         // (16, 32)
    attn_tc<<<agrid, 128, ATTN_SMEM>>>(out);
}

// round 12
// speedup vs baseline: 3.7238x; 1.0871x over previous
#include <cuda_runtime.h>
#include <cstdint>

#define BB   2
#define SS   2048
#define HH   16
#define DK   64
#define DM   1024
#define MTOT (BB*SS)   // 4096

// tf32-bit staging buffers
__device__ uint32_t g_x [MTOT*DM];      // x, same layout
__device__ uint32_t g_wt[3*DM*DM];      // W^T per sel: [n][k]
__device__ uint32_t g_q [BB*HH*SS*DK];  // [B,H,S,Dk], pre-scaled 1/8
__device__ uint32_t g_k [BB*HH*SS*DK];  // [B,H,S,Dk]
__device__ uint32_t g_v [BB*HH*SS*DK];  // [B,H,Dk,S], key-perm baked

// ---------------------------------------------------------------------------
__device__ __forceinline__ uint32_t f2tf32(float f) {
    uint32_t r;
    asm("cvt.rna.tf32.f32 %0, %1;" : "=r"(r) : "f"(f));
    return r;
}
__device__ __forceinline__ uint32_t smem_u32(const void* p) {
    uint32_t a;
    asm("{ .reg .u64 t; cvta.to.shared.u64 t, %1; cvt.u32.u64 %0, t; }"
        : "=r"(a) : "l"(p));
    return a;
}
__device__ __forceinline__ void mma8(float c[4], const uint32_t* a,
                                     const uint32_t* b) {
    asm volatile(
        "mma.sync.aligned.m16n8k8.row.col.f32.tf32.tf32.f32 "
        "{%0,%1,%2,%3}, {%4,%5,%6,%7}, {%8,%9}, {%0,%1,%2,%3};"
        : "+f"(c[0]), "+f"(c[1]), "+f"(c[2]), "+f"(c[3])
        : "r"(a[0]), "r"(a[1]), "r"(a[2]), "r"(a[3]), "r"(b[0]), "r"(b[1]));
}
__device__ __forceinline__ void ldsm4(uint32_t r[4], uint32_t addr) {
    asm volatile("ldmatrix.sync.aligned.m8n8.x4.shared.b16 {%0,%1,%2,%3}, [%4];"
                 : "=r"(r[0]), "=r"(r[1]), "=r"(r[2]), "=r"(r[3]) : "r"(addr));
}
__device__ __forceinline__ void cp16(uint32_t dst, const void* src) {
    asm volatile("cp.async.cg.shared.global [%0], [%1], 16;"
                 :: "r"(dst), "l"(src));
}
#define CP_COMMIT() asm volatile("cp.async.commit_group;" ::: "memory")
#define CP_WAIT0()  asm volatile("cp.async.wait_group 0;" ::: "memory")
#define CP_WAIT1()  asm volatile("cp.async.wait_group 1;" ::: "memory")

// ===========================================================================
// Prep: x -> tf32 bits; W -> W^T tf32 bits
// ===========================================================================
__global__ __launch_bounds__(256) void xconv(const float* __restrict__ x)
{
    int i = blockIdx.x * 1024 + threadIdx.x * 4;
    float4 v = *(const float4*)(x + i);
    *(uint4*)(g_x + i) = make_uint4(f2tf32(v.x), f2tf32(v.y),
                                    f2tf32(v.z), f2tf32(v.w));
}

__global__ __launch_bounds__(256) void wtrans(
    const float* __restrict__ Wq, const float* __restrict__ Wk,
    const float* __restrict__ Wv)
{
    __shared__ uint32_t ts[32][33];
    const int z = blockIdx.z;
    const float* W = (z == 0) ? Wq : (z == 1) ? Wk : Wv;
    const int t  = threadIdx.x;
    const int tx = t & 31, ty = t >> 5;
    const int k0 = blockIdx.x * 32, n0 = blockIdx.y * 32;
    #pragma unroll
    for (int r = 0; r < 4; r++)
        ts[ty + r * 8][tx] = f2tf32(W[(size_t)(k0 + ty + r * 8) * DM + n0 + tx]);
    __syncthreads();
    #pragma unroll
    for (int r = 0; r < 4; r++)
        g_wt[(size_t)z * DM * DM + (size_t)(n0 + ty + r * 8) * DM + k0 + tx] =
            ts[tx][ty + r * 8];
}

// ===========================================================================
// QKV GEMM v2: pure cp.async (pre-converted tf32), 3-stage, K-chunk 32,
// ldmatrix A and B frags. CTA 128x128, 8 warps (2m x 4n), warp 64x32.
// ===========================================================================
#define GLD     36                          // padded row words (128B+16)
#define G_BOFF  (128*GLD*4)                 // 18432 B
#define G_STAGE (2*128*GLD*4)               // 36864 B
#define GEMM_SMEM (3*G_STAGE)               // 110592 B

__global__ __launch_bounds__(256, 2) void qkv_gemm_tc(
    const float* __restrict__ bq, const float* __restrict__ bk,
    const float* __restrict__ bv)
{
    extern __shared__ uint32_t smg[];
    const uint32_t sb = smem_u32(smg);

    const int sel = blockIdx.z;
    const float* bias = (sel == 0) ? bq : (sel == 1) ? bk : bv;

    const int t    = threadIdx.x;
    const int wid  = t >> 5;
    const int lane = t & 31;
    const int g    = lane >> 2;
    const int tg   = lane & 3;
    const int wm   = wid & 1;
    const int wn   = wid >> 1;
    const int m0   = blockIdx.y * 128;
    const int n0   = blockIdx.x * 128;

    const int lane15  = lane & 15;
    const int lane7   = lane & 7;
    const int laneHi  = (lane >> 4) & 1;
    const int laneMid = (lane >> 3) & 1;

    // loader: thread t -> row t>>1 (0..127), col-half (t&1)*16 words
    const int lrow = t >> 1;
    const int lch  = (t & 1) * 16;
    const uint32_t* asrc0 = g_x  + (size_t)(m0 + lrow) * DM + lch;
    const uint32_t* bsrc0 = g_wt + (size_t)sel * DM * DM +
                            (size_t)(n0 + lrow) * DM + lch;
    const uint32_t ldoff = (uint32_t)((lrow * GLD + lch) * 4);

    // frag lane addresses (FIX: B includes the warp's n-section wn*32)
    const uint32_t aL = (uint32_t)(((wm * 64 + lane15) * GLD + laneHi * 4) * 4);
    const uint32_t bL = (uint32_t)(((wn * 32 + laneHi * 8 + lane7) * GLD
                                    + laneMid * 4) * 4) + (uint32_t)G_BOFF;

    float acc[4][4][4] = {};

    // prologue: issue chunk 0 -> stage 0
    #pragma unroll
    for (int c = 0; c < 4; c++) {
        cp16(sb + ldoff + (uint32_t)(c * 16), asrc0 + c * 4);
        cp16(sb + (uint32_t)G_BOFF + ldoff + (uint32_t)(c * 16), bsrc0 + c * 4);
    }
    CP_COMMIT();

    int s_cur = 0;
    for (int it = 0; it < DM / 32; it++) {
        int s_nxt = (s_cur == 2) ? 0 : s_cur + 1;
        if (it + 1 < DM / 32) {
            const uint32_t bs = sb + (uint32_t)(s_nxt * G_STAGE);
            const uint32_t* as = asrc0 + (it + 1) * 32;
            const uint32_t* ws = bsrc0 + (it + 1) * 32;
            #pragma unroll
            for (int c = 0; c < 4; c++) {
                cp16(bs + ldoff + (uint32_t)(c * 16), as + c * 4);
                cp16(bs + (uint32_t)G_BOFF + ldoff + (uint32_t)(c * 16), ws + c * 4);
            }
            CP_COMMIT();
            CP_WAIT1();
        } else {
            CP_WAIT0();
        }
        __syncthreads();

        const uint32_t stb = sb + (uint32_t)(s_cur * G_STAGE);
        const uint32_t aA  = stb + aL;
        const uint32_t bA  = stb + bL;
        #pragma unroll
        for (int kk = 0; kk < 4; kk++) {
            uint32_t a[4][4], b2[2][4];
            #pragma unroll
            for (int mi = 0; mi < 4; mi++)
                ldsm4(a[mi], aA + (uint32_t)((mi * 16 * GLD + kk * 8) * 4));
            #pragma unroll
            for (int p = 0; p < 2; p++)
                ldsm4(b2[p], bA + (uint32_t)((p * 16 * GLD + kk * 8) * 4));
            #pragma unroll
            for (int mi = 0; mi < 4; mi++)
                #pragma unroll
                for (int ni = 0; ni < 4; ni++)
                    mma8(acc[mi][ni], a[mi], b2[ni >> 1] + (ni & 1) * 2);
        }
        s_cur = s_nxt;
    }

    // ---- epilogue: +bias, convert tf32, scatter per-destination layout ----
    const int h = (n0 + wn * 32) >> 6;
    #pragma unroll
    for (int ni = 0; ni < 4; ni++) {
        int gcol = n0 + wn * 32 + ni * 8 + 2 * tg;
        int d    = gcol & 63;
        float b0 = bias[gcol], b1 = bias[gcol + 1];
        #pragma unroll
        for (int mi = 0; mi < 4; mi++) {
            int r0 = m0 + wm * 64 + mi * 16 + g;
            int r1 = r0 + 8;
            int b_0 = r0 >> 11, s0 = r0 & (SS - 1);
            int b_1 = r1 >> 11, s1 = r1 & (SS - 1);
            float v00 = acc[mi][ni][0] + b0, v01 = acc[mi][ni][1] + b1;
            float v10 = acc[mi][ni][2] + b0, v11 = acc[mi][ni][3] + b1;
            if (sel == 0) {
                uint32_t* p0 = g_q + (((size_t)(b_0 * HH + h) * SS + s0) * DK) + d;
                uint32_t* p1 = g_q + (((size_t)(b_1 * HH + h) * SS + s1) * DK) + d;
                *(uint2*)p0 = make_uint2(f2tf32(v00 * 0.125f), f2tf32(v01 * 0.125f));
                *(uint2*)p1 = make_uint2(f2tf32(v10 * 0.125f), f2tf32(v11 * 0.125f));
            } else if (sel == 1) {
                uint32_t* p0 = g_k + (((size_t)(b_0 * HH + h) * SS + s0) * DK) + d;
                uint32_t* p1 = g_k + (((size_t)(b_1 * HH + h) * SS + s1) * DK) + d;
                *(uint2*)p0 = make_uint2(f2tf32(v00), f2tf32(v01));
                *(uint2*)p1 = make_uint2(f2tf32(v10), f2tf32(v11));
            } else {
                int s0p = (s0 & ~7) | ((s0 >> 1) & 3) | ((s0 & 1) << 2);
                int s1p = (s1 & ~7) | ((s1 >> 1) & 3) | ((s1 & 1) << 2);
                uint32_t* vb = g_v + ((size_t)(b_0 * HH + h) * DK + d) * SS;
                vb[s0p]      = f2tf32(v00);
                vb[SS + s0p] = f2tf32(v01);
                uint32_t* vb1 = g_v + ((size_t)(b_1 * HH + h) * DK + d) * SS;
                vb1[s1p]      = f2tf32(v10);
                vb1[SS + s1p] = f2tf32(v11);
            }
        }
    }
}

// ===========================================================================
// Flash attention v6: 3-stage cp.async ring, ONE barrier per tile.
// 128 threads, 4 warps x 32q, BK=64; P in registers (C->A frag reuse).
// ===========================================================================
#define KLD   68
#define BUFW  (64 * KLD)                    // words per K (or V) buffer
#define A_STAGE (2 * BUFW * 4)              // 34816 B (K then V)
#define ATTN_SMEM (3 * A_STAGE)             // 104448 B

__global__ __launch_bounds__(128, 2) void attn_tc(float* __restrict__ out)
{
    extern __shared__ uint32_t sm[];
    const uint32_t sb = smem_u32(sm);

    const int t    = threadIdx.x;
    const int wid  = t >> 5;
    const int lane = t & 31;
    const int g    = lane >> 2;
    const int tg   = lane & 3;
    const int bh   = blockIdx.y;
    const int q0   = blockIdx.x * 128;

    const uint32_t* Qp = g_q + ((size_t)bh * SS + q0) * DK;
    const uint32_t* Kp = g_k + (size_t)bh * SS * DK;
    const uint32_t* Vp = g_v + (size_t)bh * DK * SS;

    // ---- stage Q into stage-0 region, extract frags ----
    #pragma unroll
    for (int c = 0; c < 16; c++)
        cp16(sb + (uint32_t)((t * KLD + c * 4) * 4), Qp + (size_t)t * DK + c * 4);
    CP_COMMIT();
    CP_WAIT0();
    __syncthreads();

    const int lane15  = lane & 15;
    const int lane7   = lane & 7;
    const int laneHi  = (lane >> 4) & 1;
    const int laneMid = (lane >> 3) & 1;
    const int arow0   = wid * 32;

    uint32_t qf[2][8][4];
    #pragma unroll
    for (int mt = 0; mt < 2; mt++) {
        uint32_t qa = sb +
            (uint32_t)(((arow0 + mt * 16 + lane15) * KLD + laneHi * 4) * 4);
        #pragma unroll
        for (int k0 = 0; k0 < 8; k0++)
            ldsm4(qf[mt][k0], qa + (uint32_t)(k0 * 32));
    }
    __syncthreads();   // Q frags read before tile0 overwrites stage 0

    // loader: thread t -> key row t>>1 (0..63), col-half (t&1)*32
    const int lrow = t >> 1;
    const int lcol = (t & 1) * 32;
    const uint32_t kld = (uint32_t)((lrow * KLD + lcol) * 4);

    const uint32_t kaL = (uint32_t)(((laneHi * 8 + lane7) * KLD + laneMid * 4) * 4);
    const uint32_t vaL = kaL + (uint32_t)(BUFW * 4);

    float cacc[2][8][4] = {};
    float rs[2][2] = {};

    // issue tile 0 -> stage 0
    {
        const uint32_t* ks = Kp + (size_t)lrow * DK + lcol;
        const uint32_t* vs = Vp + (size_t)lrow * SS + lcol;
        #pragma unroll
        for (int c = 0; c < 8; c++) {
            cp16(sb + kld + (uint32_t)(c * 16), ks + c * 4);
            cp16(sb + (uint32_t)(BUFW * 4) + kld + (uint32_t)(c * 16), vs + c * 4);
        }
        CP_COMMIT();
    }

    int s_cur = 0;
    for (int kt = 0; kt < SS / 64; kt++) {
        int s_nxt = (s_cur == 2) ? 0 : s_cur + 1;
        if (kt + 1 < SS / 64) {
            const uint32_t bs = sb + (uint32_t)(s_nxt * A_STAGE);
            const uint32_t* ks = Kp + (size_t)((kt + 1) * 64 + lrow) * DK + lcol;
            const uint32_t* vs = Vp + (size_t)lrow * SS + (kt + 1) * 64 + lcol;
            #pragma unroll
            for (int c = 0; c < 8; c++) {
                cp16(bs + kld + (uint32_t)(c * 16), ks + c * 4);
                cp16(bs + (uint32_t)(BUFW * 4) + kld + (uint32_t)(c * 16), vs + c * 4);
            }
            CP_COMMIT();
            CP_WAIT1();
        } else {
            CP_WAIT0();
        }
        __syncthreads();   // the only barrier per tile

        const uint32_t stb = sb + (uint32_t)(s_cur * A_STAGE);
        const uint32_t kac = stb + kaL;
        const uint32_t vac = stb + vaL;

        // ---- S = (Q/8) K^T : 32q x 64k per warp ----
        float sc[2][8][4] = {};
        #pragma unroll
        for (int k0 = 0; k0 < 8; k0++) {
            #pragma unroll
            for (int ni = 0; ni < 8; ni += 2) {
                uint32_t b[4];
                ldsm4(b, kac + (uint32_t)((ni * 8 * KLD + k0 * 8) * 4));
                mma8(sc[0][ni],     qf[0][k0], b);
                mma8(sc[0][ni + 1], qf[0][k0], b + 2);
                mma8(sc[1][ni],     qf[1][k0], b);
                mma8(sc[1][ni + 1], qf[1][k0], b + 2);
            }
        }

        // ---- P = exp(S) in registers; C-frag -> A-frag ({c0,c2,c1,c3}) ----
        uint32_t pf[2][8][4];
        #pragma unroll
        for (int mt = 0; mt < 2; mt++) {
            #pragma unroll
            for (int ni = 0; ni < 8; ni++) {
                float e0 = __expf(sc[mt][ni][0]);
                float e1 = __expf(sc[mt][ni][1]);
                float e2 = __expf(sc[mt][ni][2]);
                float e3 = __expf(sc[mt][ni][3]);
                rs[mt][0] += e0 + e1;
                rs[mt][1] += e2 + e3;
                pf[mt][ni][0] = f2tf32(e0);
                pf[mt][ni][1] = f2tf32(e2);
                pf[mt][ni][2] = f2tf32(e1);
                pf[mt][ni][3] = f2tf32(e3);
            }
        }

        // ---- ctx += P V ----
        #pragma unroll
        for (int ni = 0; ni < 8; ni++) {
            #pragma unroll
            for (int dt = 0; dt < 8; dt += 2) {
                uint32_t b[4];
                ldsm4(b, vac + (uint32_t)((dt * 8 * KLD + ni * 8) * 4));
                mma8(cacc[0][dt],     pf[0][ni], b);
                mma8(cacc[0][dt + 1], pf[0][ni], b + 2);
                mma8(cacc[1][dt],     pf[1][ni], b);
                mma8(cacc[1][dt + 1], pf[1][ni], b + 2);
            }
        }
        s_cur = s_nxt;
    }

    // ---- rowsum quad-reduce, normalize, store ----
    #pragma unroll
    for (int mt = 0; mt < 2; mt++) {
        rs[mt][0] += __shfl_xor_sync(0xFFFFFFFF, rs[mt][0], 1);
        rs[mt][0] += __shfl_xor_sync(0xFFFFFFFF, rs[mt][0], 2);
        rs[mt][1] += __shfl_xor_sync(0xFFFFFFFF, rs[mt][1], 1);
        rs[mt][1] += __shfl_xor_sync(0xFFFFFFFF, rs[mt][1], 2);
    }

    const int b_ = bh / HH;
    const int h  = bh % HH;
    #pragma unroll
    for (int mt = 0; mt < 2; mt++) {
        const float inv0 = 1.f / (rs[mt][0] + 1e-8f);
        const float inv1 = 1.f / (rs[mt][1] + 1e-8f);
        const int r0 = q0 + arow0 + mt * 16 + g;
        const int r1 = r0 + 8;
        float* o0 = out + (size_t)(b_ * SS + r0) * DM + h * DK;
        float* o1 = out + (size_t)(b_ * SS + r1) * DM + h * DK;
        #pragma unroll
        for (int ni = 0; ni < 8; ni++) {
            int d = ni * 8 + 2 * tg;
            *(float2*)(o0 + d) =
                make_float2(cacc[mt][ni][0] * inv0, cacc[mt][ni][1] * inv0);
            *(float2*)(o1 + d) =
                make_float2(cacc[mt][ni][2] * inv1, cacc[mt][ni][3] * inv1);
        }
    }
}

// ===========================================================================
extern "C" void kernel_launch(void* const* d_in, const int* in_sizes, int n_in,
                              void* d_out, int out_size)
{
    const float* x  = (const float*)d_in[0];
    const float* Wq = (const float*)d_in[1];
    const float* bq = (const float*)d_in[2];
    const float* Wk = (const float*)d_in[3];
    const float* bk = (const float*)d_in[4];
    const float* Wv = (const float*)d_in[5];
    const float* bv = (const float*)d_in[6];
    float* out = (float*)d_out;

    cudaFuncSetAttribute(qkv_gemm_tc,
                         cudaFuncAttributeMaxDynamicSharedMemorySize, GEMM_SMEM);
    cudaFuncSetAttribute(attn_tc,
                         cudaFuncAttributeMaxDynamicSharedMemorySize, ATTN_SMEM);

    xconv<<<MTOT, 256>>>(x);
    wtrans<<<dim3(32, 32, 3), 256>>>(Wq, Wk, Wv);

    dim3 ggrid(DM / 128, MTOT / 128, 3);   // (8, 32, 3)
    qkv_gemm_tc<<<ggrid, 256, GEMM_SMEM>>>(bq, bk, bv);

    dim3 agrid(SS / 128, BB * HH);         // (16, 32)
    attn_tc<<<agrid, 128, ATTN_SMEM>>>(out);
}

// round 14
// speedup vs baseline: 3.9312x; 1.0557x over previous
#include <cuda_runtime.h>
#include <cstdint>

#define BB   2
#define SS   2048
#define HH   16
#define DK   64
#define DM   1024
#define MTOT (BB*SS)   // 4096

// tf32-bit staging buffers
__device__ uint32_t g_x [MTOT*DM];      // x, same layout
__device__ uint32_t g_wt[3*DM*DM];      // W^T per sel: [n][k]
__device__ uint32_t g_q [BB*HH*SS*DK];  // [B,H,S,Dk], pre-scaled 1/8
__device__ uint32_t g_k [BB*HH*SS*DK];  // [B,H,S,Dk]
__device__ uint32_t g_v [BB*HH*SS*DK];  // [B,H,Dk,S], key-perm baked

// ---------------------------------------------------------------------------
__device__ __forceinline__ uint32_t f2tf32(float f) {
    uint32_t r;
    asm("cvt.rna.tf32.f32 %0, %1;" : "=r"(r) : "f"(f));
    return r;
}
__device__ __forceinline__ uint32_t smem_u32(const void* p) {
    uint32_t a;
    asm("{ .reg .u64 t; cvta.to.shared.u64 t, %1; cvt.u32.u64 %0, t; }"
        : "=r"(a) : "l"(p));
    return a;
}
__device__ __forceinline__ void mma8(float c[4], const uint32_t* a,
                                     const uint32_t* b) {
    asm volatile(
        "mma.sync.aligned.m16n8k8.row.col.f32.tf32.tf32.f32 "
        "{%0,%1,%2,%3}, {%4,%5,%6,%7}, {%8,%9}, {%0,%1,%2,%3};"
        : "+f"(c[0]), "+f"(c[1]), "+f"(c[2]), "+f"(c[3])
        : "r"(a[0]), "r"(a[1]), "r"(a[2]), "r"(a[3]), "r"(b[0]), "r"(b[1]));
}
__device__ __forceinline__ void ldsm4(uint32_t r[4], uint32_t addr) {
    asm volatile("ldmatrix.sync.aligned.m8n8.x4.shared.b16 {%0,%1,%2,%3}, [%4];"
                 : "=r"(r[0]), "=r"(r[1]), "=r"(r[2]), "=r"(r[3]) : "r"(addr));
}
__device__ __forceinline__ void cp16(uint32_t dst, const void* src) {
    asm volatile("cp.async.cg.shared.global [%0], [%1], 16;"
                 :: "r"(dst), "l"(src));
}
#define CP_COMMIT() asm volatile("cp.async.commit_group;" ::: "memory")
#define CP_WAIT0()  asm volatile("cp.async.wait_group 0;" ::: "memory")
#define CP_WAIT1()  asm volatile("cp.async.wait_group 1;" ::: "memory")

// ===========================================================================
// Prep: x -> tf32 bits; W -> W^T tf32 bits
// ===========================================================================
__global__ __launch_bounds__(256) void xconv(const float* __restrict__ x)
{
    int i = blockIdx.x * 1024 + threadIdx.x * 4;
    float4 v = *(const float4*)(x + i);
    *(uint4*)(g_x + i) = make_uint4(f2tf32(v.x), f2tf32(v.y),
                                    f2tf32(v.z), f2tf32(v.w));
}

__global__ __launch_bounds__(256) void wtrans(
    const float* __restrict__ Wq, const float* __restrict__ Wk,
    const float* __restrict__ Wv)
{
    __shared__ uint32_t ts[32][33];
    const int z = blockIdx.z;
    const float* W = (z == 0) ? Wq : (z == 1) ? Wk : Wv;
    const int t  = threadIdx.x;
    const int tx = t & 31, ty = t >> 5;
    const int k0 = blockIdx.x * 32, n0 = blockIdx.y * 32;
    #pragma unroll
    for (int r = 0; r < 4; r++)
        ts[ty + r * 8][tx] = f2tf32(W[(size_t)(k0 + ty + r * 8) * DM + n0 + tx]);
    __syncthreads();
    #pragma unroll
    for (int r = 0; r < 4; r++)
        g_wt[(size_t)z * DM * DM + (size_t)(n0 + ty + r * 8) * DM + k0 + tx] =
            ts[tx][ty + r * 8];
}

// ===========================================================================
// QKV GEMM v2 (unchanged from R12): pure cp.async, 3-stage, K-chunk 32.
// ===========================================================================
#define GLD     36
#define G_BOFF  (128*GLD*4)
#define G_STAGE (2*128*GLD*4)
#define GEMM_SMEM (3*G_STAGE)               // 110592 B

__global__ __launch_bounds__(256, 2) void qkv_gemm_tc(
    const float* __restrict__ bq, const float* __restrict__ bk,
    const float* __restrict__ bv)
{
    extern __shared__ uint32_t smg[];
    const uint32_t sb = smem_u32(smg);

    const int sel = blockIdx.z;
    const float* bias = (sel == 0) ? bq : (sel == 1) ? bk : bv;

    const int t    = threadIdx.x;
    const int wid  = t >> 5;
    const int lane = t & 31;
    const int g    = lane >> 2;
    const int tg   = lane & 3;
    const int wm   = wid & 1;
    const int wn   = wid >> 1;
    const int m0   = blockIdx.y * 128;
    const int n0   = blockIdx.x * 128;

    const int lane15  = lane & 15;
    const int lane7   = lane & 7;
    const int laneHi  = (lane >> 4) & 1;
    const int laneMid = (lane >> 3) & 1;

    const int lrow = t >> 1;
    const int lch  = (t & 1) * 16;
    const uint32_t* asrc0 = g_x  + (size_t)(m0 + lrow) * DM + lch;
    const uint32_t* bsrc0 = g_wt + (size_t)sel * DM * DM +
                            (size_t)(n0 + lrow) * DM + lch;
    const uint32_t ldoff = (uint32_t)((lrow * GLD + lch) * 4);

    const uint32_t aL = (uint32_t)(((wm * 64 + lane15) * GLD + laneHi * 4) * 4);
    const uint32_t bL = (uint32_t)(((wn * 32 + laneHi * 8 + lane7) * GLD
                                    + laneMid * 4) * 4) + (uint32_t)G_BOFF;

    float acc[4][4][4] = {};

    #pragma unroll
    for (int c = 0; c < 4; c++) {
        cp16(sb + ldoff + (uint32_t)(c * 16), asrc0 + c * 4);
        cp16(sb + (uint32_t)G_BOFF + ldoff + (uint32_t)(c * 16), bsrc0 + c * 4);
    }
    CP_COMMIT();

    int s_cur = 0;
    for (int it = 0; it < DM / 32; it++) {
        int s_nxt = (s_cur == 2) ? 0 : s_cur + 1;
        if (it + 1 < DM / 32) {
            const uint32_t bs = sb + (uint32_t)(s_nxt * G_STAGE);
            const uint32_t* as = asrc0 + (it + 1) * 32;
            const uint32_t* ws = bsrc0 + (it + 1) * 32;
            #pragma unroll
            for (int c = 0; c < 4; c++) {
                cp16(bs + ldoff + (uint32_t)(c * 16), as + c * 4);
                cp16(bs + (uint32_t)G_BOFF + ldoff + (uint32_t)(c * 16), ws + c * 4);
            }
            CP_COMMIT();
            CP_WAIT1();
        } else {
            CP_WAIT0();
        }
        __syncthreads();

        const uint32_t stb = sb + (uint32_t)(s_cur * G_STAGE);
        const uint32_t aA  = stb + aL;
        const uint32_t bA  = stb + bL;
        #pragma unroll
        for (int kk = 0; kk < 4; kk++) {
            uint32_t a[4][4], b2[2][4];
            #pragma unroll
            for (int mi = 0; mi < 4; mi++)
                ldsm4(a[mi], aA + (uint32_t)((mi * 16 * GLD + kk * 8) * 4));
            #pragma unroll
            for (int p = 0; p < 2; p++)
                ldsm4(b2[p], bA + (uint32_t)((p * 16 * GLD + kk * 8) * 4));
            #pragma unroll
            for (int mi = 0; mi < 4; mi++)
                #pragma unroll
                for (int ni = 0; ni < 4; ni++)
                    mma8(acc[mi][ni], a[mi], b2[ni >> 1] + (ni & 1) * 2);
        }
        s_cur = s_nxt;
    }

    const int h = (n0 + wn * 32) >> 6;
    #pragma unroll
    for (int ni = 0; ni < 4; ni++) {
        int gcol = n0 + wn * 32 + ni * 8 + 2 * tg;
        int d    = gcol & 63;
        float b0 = bias[gcol], b1 = bias[gcol + 1];
        #pragma unroll
        for (int mi = 0; mi < 4; mi++) {
            int r0 = m0 + wm * 64 + mi * 16 + g;
            int r1 = r0 + 8;
            int b_0 = r0 >> 11, s0 = r0 & (SS - 1);
            int b_1 = r1 >> 11, s1 = r1 & (SS - 1);
            float v00 = acc[mi][ni][0] + b0, v01 = acc[mi][ni][1] + b1;
            float v10 = acc[mi][ni][2] + b0, v11 = acc[mi][ni][3] + b1;
            if (sel == 0) {
                uint32_t* p0 = g_q + (((size_t)(b_0 * HH + h) * SS + s0) * DK) + d;
                uint32_t* p1 = g_q + (((size_t)(b_1 * HH + h) * SS + s1) * DK) + d;
                *(uint2*)p0 = make_uint2(f2tf32(v00 * 0.125f), f2tf32(v01 * 0.125f));
                *(uint2*)p1 = make_uint2(f2tf32(v10 * 0.125f), f2tf32(v11 * 0.125f));
            } else if (sel == 1) {
                uint32_t* p0 = g_k + (((size_t)(b_0 * HH + h) * SS + s0) * DK) + d;
                uint32_t* p1 = g_k + (((size_t)(b_1 * HH + h) * SS + s1) * DK) + d;
                *(uint2*)p0 = make_uint2(f2tf32(v00), f2tf32(v01));
                *(uint2*)p1 = make_uint2(f2tf32(v10), f2tf32(v11));
            } else {
                int s0p = (s0 & ~7) | ((s0 >> 1) & 3) | ((s0 & 1) << 2);
                int s1p = (s1 & ~7) | ((s1 >> 1) & 3) | ((s1 & 1) << 2);
                uint32_t* vb = g_v + ((size_t)(b_0 * HH + h) * DK + d) * SS;
                vb[s0p]      = f2tf32(v00);
                vb[SS + s0p] = f2tf32(v01);
                uint32_t* vb1 = g_v + ((size_t)(b_1 * HH + h) * DK + d) * SS;
                vb1[s1p]      = f2tf32(v10);
                vb1[SS + s1p] = f2tf32(v11);
            }
        }
    }
}

// ===========================================================================
// Flash attention v7: 256 threads, 8 warps x 16q (2x warps/SMSP vs v6).
// P bits overwrite the S accumulator array (no extra registers).
// 3-stage cp.async ring, one barrier per tile.
// ===========================================================================
#define KLD   68
#define BUFW  (64 * KLD)
#define A_STAGE (2 * BUFW * 4)              // 34816 B
#define ATTN_SMEM (3 * A_STAGE)             // 104448 B

__global__ __launch_bounds__(256, 2) void attn_tc(float* __restrict__ out)
{
    extern __shared__ uint32_t sm[];
    const uint32_t sb = smem_u32(sm);

    const int t    = threadIdx.x;
    const int wid  = t >> 5;
    const int lane = t & 31;
    const int g    = lane >> 2;
    const int tg   = lane & 3;
    const int bh   = blockIdx.y;
    const int q0   = blockIdx.x * 128;

    const uint32_t* Qp = g_q + ((size_t)bh * SS + q0) * DK;
    const uint32_t* Kp = g_k + (size_t)bh * SS * DK;
    const uint32_t* Vp = g_v + (size_t)bh * DK * SS;

    // ---- stage Q (128 rows x 64 words) into stage-0 region ----
    {
        const int qrow = t >> 1;
        const int qcol = (t & 1) * 32;
        #pragma unroll
        for (int c = 0; c < 8; c++)
            cp16(sb + (uint32_t)((qrow * KLD + qcol + c * 4) * 4),
                 Qp + (size_t)qrow * DK + qcol + c * 4);
    }
    CP_COMMIT();
    CP_WAIT0();
    __syncthreads();

    const int lane15  = lane & 15;
    const int lane7   = lane & 7;
    const int laneHi  = (lane >> 4) & 1;
    const int laneMid = (lane >> 3) & 1;
    const int arow0   = wid * 16;          // 16-q band per warp

    // ---- extract Q fragments (one m16 tile per warp) ----
    uint32_t qf[8][4];
    {
        uint32_t qa = sb +
            (uint32_t)(((arow0 + lane15) * KLD + laneHi * 4) * 4);
        #pragma unroll
        for (int k0 = 0; k0 < 8; k0++)
            ldsm4(qf[k0], qa + (uint32_t)(k0 * 32));
    }
    __syncthreads();   // Q frags read before tile0 overwrites stage 0

    // loader: thread t -> key row t>>2, quarter (t&3)*16 words (4 cp16 each)
    const int lrow = t >> 2;
    const int lcol = (t & 3) * 16;
    const uint32_t kld = (uint32_t)((lrow * KLD + lcol) * 4);

    const uint32_t kaL = (uint32_t)(((laneHi * 8 + lane7) * KLD + laneMid * 4) * 4);
    const uint32_t vaL = kaL + (uint32_t)(BUFW * 4);

    float cacc[8][4] = {};
    float rs[2] = {0.f, 0.f};

    // issue tile 0 -> stage 0
    {
        const uint32_t* ks = Kp + (size_t)lrow * DK + lcol;
        const uint32_t* vs = Vp + (size_t)lrow * SS + lcol;
        #pragma unroll
        for (int c = 0; c < 4; c++) {
            cp16(sb + kld + (uint32_t)(c * 16), ks + c * 4);
            cp16(sb + (uint32_t)(BUFW * 4) + kld + (uint32_t)(c * 16), vs + c * 4);
        }
        CP_COMMIT();
    }

    int s_cur = 0;
    for (int kt = 0; kt < SS / 64; kt++) {
        int s_nxt = (s_cur == 2) ? 0 : s_cur + 1;
        if (kt + 1 < SS / 64) {
            const uint32_t bs = sb + (uint32_t)(s_nxt * A_STAGE);
            const uint32_t* ks = Kp + (size_t)((kt + 1) * 64 + lrow) * DK + lcol;
            const uint32_t* vs = Vp + (size_t)lrow * SS + (kt + 1) * 64 + lcol;
            #pragma unroll
            for (int c = 0; c < 4; c++) {
                cp16(bs + kld + (uint32_t)(c * 16), ks + c * 4);
                cp16(bs + (uint32_t)(BUFW * 4) + kld + (uint32_t)(c * 16), vs + c * 4);
            }
            CP_COMMIT();
            CP_WAIT1();
        } else {
            CP_WAIT0();
        }
        __syncthreads();   // the only barrier per tile

        const uint32_t stb = sb + (uint32_t)(s_cur * A_STAGE);
        const uint32_t kac = stb + kaL;
        const uint32_t vac = stb + vaL;

        // ---- S = (Q/8) K^T : 16q x 64k per warp ----
        float sc[8][4] = {};
        #pragma unroll
        for (int k0 = 0; k0 < 8; k0++) {
            #pragma unroll
            for (int ni = 0; ni < 8; ni += 2) {
                uint32_t b[4];
                ldsm4(b, kac + (uint32_t)((ni * 8 * KLD + k0 * 8) * 4));
                mma8(sc[ni],     qf[k0], b);
                mma8(sc[ni + 1], qf[k0], b + 2);
            }
        }

        // ---- P = exp(S), bits stored IN PLACE over sc ({e0,e2,e1,e3}) ----
        #pragma unroll
        for (int ni = 0; ni < 8; ni++) {
            float e0 = __expf(sc[ni][0]);
            float e1 = __expf(sc[ni][1]);
            float e2 = __expf(sc[ni][2]);
            float e3 = __expf(sc[ni][3]);
            rs[0] += e0 + e1;
            rs[1] += e2 + e3;
            sc[ni][0] = __uint_as_float(f2tf32(e0));
            sc[ni][1] = __uint_as_float(f2tf32(e2));
            sc[ni][2] = __uint_as_float(f2tf32(e1));
            sc[ni][3] = __uint_as_float(f2tf32(e3));
        }

        // ---- ctx += P V (A-frags are the sc bit patterns) ----
        #pragma unroll
        for (int ni = 0; ni < 8; ni++) {
            const uint32_t* pa = (const uint32_t*)sc[ni];
            #pragma unroll
            for (int dt = 0; dt < 8; dt += 2) {
                uint32_t b[4];
                ldsm4(b, vac + (uint32_t)((dt * 8 * KLD + ni * 8) * 4));
                mma8(cacc[dt],     pa, b);
                mma8(cacc[dt + 1], pa, b + 2);
            }
        }
        s_cur = s_nxt;
    }

    // ---- rowsum quad-reduce, normalize, store ----
    rs[0] += __shfl_xor_sync(0xFFFFFFFF, rs[0], 1);
    rs[0] += __shfl_xor_sync(0xFFFFFFFF, rs[0], 2);
    rs[1] += __shfl_xor_sync(0xFFFFFFFF, rs[1], 1);
    rs[1] += __shfl_xor_sync(0xFFFFFFFF, rs[1], 2);
    const float inv0 = 1.f / (rs[0] + 1e-8f);
    const float inv1 = 1.f / (rs[1] + 1e-8f);

    const int b_ = bh / HH;
    const int h  = bh % HH;
    const int r0 = q0 + arow0 + g;
    const int r1 = r0 + 8;
    float* o0 = out + (size_t)(b_ * SS + r0) * DM + h * DK;
    float* o1 = out + (size_t)(b_ * SS + r1) * DM + h * DK;
    #pragma unroll
    for (int ni = 0; ni < 8; ni++) {
        int d = ni * 8 + 2 * tg;
        *(float2*)(o0 + d) = make_float2(cacc[ni][0] * inv0, cacc[ni][1] * inv0);
        *(float2*)(o1 + d) = make_float2(cacc[ni][2] * inv1, cacc[ni][3] * inv1);
    }
}

// ===========================================================================
extern "C" void kernel_launch(void* const* d_in, const int* in_sizes, int n_in,
                              void* d_out, int out_size)
{
    const float* x  = (const float*)d_in[0];
    const float* Wq = (const float*)d_in[1];
    const float* bq = (const float*)d_in[2];
    const float* Wk = (const float*)d_in[3];
    const float* bk = (const float*)d_in[4];
    const float* Wv = (const float*)d_in[5];
    const float* bv = (const float*)d_in[6];
    float* out = (float*)d_out;

    cudaFuncSetAttribute(qkv_gemm_tc,
                         cudaFuncAttributeMaxDynamicSharedMemorySize, GEMM_SMEM);
    cudaFuncSetAttribute(attn_tc,
                         cudaFuncAttributeMaxDynamicSharedMemorySize, ATTN_SMEM);

    xconv<<<MTOT, 256>>>(x);
    wtrans<<<dim3(32, 32, 3), 256>>>(Wq, Wk, Wv);

    dim3 ggrid(DM / 128, MTOT / 128, 3);   // (8, 32, 3)
    qkv_gemm_tc<<<ggrid, 256, GEMM_SMEM>>>(bq, bk, bv);

    dim3 agrid(SS / 128, BB * HH);         // (16, 32)
    attn_tc<<<agrid, 256, ATTN_SMEM>>>(out);
}

// round 15
// speedup vs baseline: 3.9814x; 1.0128x over previous
#include <cuda_runtime.h>
#include <cstdint>

#define BB   2
#define SS   2048
#define HH   16
#define DK   64
#define DM   1024
#define MTOT (BB*SS)   // 4096

// tf32-bit staging buffers
__device__ uint32_t g_x [MTOT*DM];      // x, same layout
__device__ uint32_t g_wt[3*DM*DM];      // W^T per sel: [n][k]
__device__ uint32_t g_q [BB*HH*SS*DK];  // [B,H,S,Dk], pre-scaled by log2e/8
__device__ uint32_t g_k [BB*HH*SS*DK];  // [B,H,S,Dk]
__device__ uint32_t g_v [BB*HH*SS*DK];  // [B,H,Dk,S], key-perm baked

// ---------------------------------------------------------------------------
__device__ __forceinline__ uint32_t f2tf32(float f) {
    uint32_t r;
    asm("cvt.rna.tf32.f32 %0, %1;" : "=r"(r) : "f"(f));
    return r;
}
__device__ __forceinline__ float ex2f(float x) {
    float r;
    asm("ex2.approx.f32 %0, %1;" : "=f"(r) : "f"(x));
    return r;
}
__device__ __forceinline__ uint32_t smem_u32(const void* p) {
    uint32_t a;
    asm("{ .reg .u64 t; cvta.to.shared.u64 t, %1; cvt.u32.u64 %0, t; }"
        : "=r"(a) : "l"(p));
    return a;
}
__device__ __forceinline__ void mma8(float c[4], const uint32_t* a,
                                     const uint32_t* b) {
    asm volatile(
        "mma.sync.aligned.m16n8k8.row.col.f32.tf32.tf32.f32 "
        "{%0,%1,%2,%3}, {%4,%5,%6,%7}, {%8,%9}, {%0,%1,%2,%3};"
        : "+f"(c[0]), "+f"(c[1]), "+f"(c[2]), "+f"(c[3])
        : "r"(a[0]), "r"(a[1]), "r"(a[2]), "r"(a[3]), "r"(b[0]), "r"(b[1]));
}
__device__ __forceinline__ void ldsm4(uint32_t r[4], uint32_t addr) {
    asm volatile("ldmatrix.sync.aligned.m8n8.x4.shared.b16 {%0,%1,%2,%3}, [%4];"
                 : "=r"(r[0]), "=r"(r[1]), "=r"(r[2]), "=r"(r[3]) : "r"(addr));
}
__device__ __forceinline__ void cp16(uint32_t dst, const void* src) {
    asm volatile("cp.async.cg.shared.global [%0], [%1], 16;"
                 :: "r"(dst), "l"(src));
}
#define CP_COMMIT() asm volatile("cp.async.commit_group;" ::: "memory")
#define CP_WAIT0()  asm volatile("cp.async.wait_group 0;" ::: "memory")
#define CP_WAIT1()  asm volatile("cp.async.wait_group 1;" ::: "memory")

// ===========================================================================
// Prep: x -> tf32 bits; W -> W^T tf32 bits
// ===========================================================================
__global__ __launch_bounds__(256) void xconv(const float* __restrict__ x)
{
    int i = blockIdx.x * 1024 + threadIdx.x * 4;
    float4 v = *(const float4*)(x + i);
    *(uint4*)(g_x + i) = make_uint4(f2tf32(v.x), f2tf32(v.y),
                                    f2tf32(v.z), f2tf32(v.w));
}

__global__ __launch_bounds__(256) void wtrans(
    const float* __restrict__ Wq, const float* __restrict__ Wk,
    const float* __restrict__ Wv)
{
    __shared__ uint32_t ts[32][33];
    const int z = blockIdx.z;
    const float* W = (z == 0) ? Wq : (z == 1) ? Wk : Wv;
    const int t  = threadIdx.x;
    const int tx = t & 31, ty = t >> 5;
    const int k0 = blockIdx.x * 32, n0 = blockIdx.y * 32;
    #pragma unroll
    for (int r = 0; r < 4; r++)
        ts[ty + r * 8][tx] = f2tf32(W[(size_t)(k0 + ty + r * 8) * DM + n0 + tx]);
    __syncthreads();
    #pragma unroll
    for (int r = 0; r < 4; r++)
        g_wt[(size_t)z * DM * DM + (size_t)(n0 + ty + r * 8) * DM + k0 + tx] =
            ts[tx][ty + r * 8];
}

// ===========================================================================
// QKV GEMM v2 (unchanged): pure cp.async, 3-stage, K-chunk 32.
// Q prescale now 0.125*log2(e) so attention can use raw ex2.
// ===========================================================================
#define GLD     36
#define G_BOFF  (128*GLD*4)
#define G_STAGE (2*128*GLD*4)
#define GEMM_SMEM (3*G_STAGE)               // 110592 B
#define QSCALE  0.18033688f                 // 0.125 * log2(e)

__global__ __launch_bounds__(256, 2) void qkv_gemm_tc(
    const float* __restrict__ bq, const float* __restrict__ bk,
    const float* __restrict__ bv)
{
    extern __shared__ uint32_t smg[];
    const uint32_t sb = smem_u32(smg);

    const int sel = blockIdx.z;
    const float* bias = (sel == 0) ? bq : (sel == 1) ? bk : bv;

    const int t    = threadIdx.x;
    const int wid  = t >> 5;
    const int lane = t & 31;
    const int g    = lane >> 2;
    const int tg   = lane & 3;
    const int wm   = wid & 1;
    const int wn   = wid >> 1;
    const int m0   = blockIdx.y * 128;
    const int n0   = blockIdx.x * 128;

    const int lane15  = lane & 15;
    const int lane7   = lane & 7;
    const int laneHi  = (lane >> 4) & 1;
    const int laneMid = (lane >> 3) & 1;

    const int lrow = t >> 1;
    const int lch  = (t & 1) * 16;
    const uint32_t* asrc0 = g_x  + (size_t)(m0 + lrow) * DM + lch;
    const uint32_t* bsrc0 = g_wt + (size_t)sel * DM * DM +
                            (size_t)(n0 + lrow) * DM + lch;
    const uint32_t ldoff = (uint32_t)((lrow * GLD + lch) * 4);

    const uint32_t aL = (uint32_t)(((wm * 64 + lane15) * GLD + laneHi * 4) * 4);
    const uint32_t bL = (uint32_t)(((wn * 32 + laneHi * 8 + lane7) * GLD
                                    + laneMid * 4) * 4) + (uint32_t)G_BOFF;

    float acc[4][4][4] = {};

    #pragma unroll
    for (int c = 0; c < 4; c++) {
        cp16(sb + ldoff + (uint32_t)(c * 16), asrc0 + c * 4);
        cp16(sb + (uint32_t)G_BOFF + ldoff + (uint32_t)(c * 16), bsrc0 + c * 4);
    }
    CP_COMMIT();

    int s_cur = 0;
    for (int it = 0; it < DM / 32; it++) {
        int s_nxt = (s_cur == 2) ? 0 : s_cur + 1;
        if (it + 1 < DM / 32) {
            const uint32_t bs = sb + (uint32_t)(s_nxt * G_STAGE);
            const uint32_t* as = asrc0 + (it + 1) * 32;
            const uint32_t* ws = bsrc0 + (it + 1) * 32;
            #pragma unroll
            for (int c = 0; c < 4; c++) {
                cp16(bs + ldoff + (uint32_t)(c * 16), as + c * 4);
                cp16(bs + (uint32_t)G_BOFF + ldoff + (uint32_t)(c * 16), ws + c * 4);
            }
            CP_COMMIT();
            CP_WAIT1();
        } else {
            CP_WAIT0();
        }
        __syncthreads();

        const uint32_t stb = sb + (uint32_t)(s_cur * G_STAGE);
        const uint32_t aA  = stb + aL;
        const uint32_t bA  = stb + bL;
        #pragma unroll
        for (int kk = 0; kk < 4; kk++) {
            uint32_t a[4][4], b2[2][4];
            #pragma unroll
            for (int mi = 0; mi < 4; mi++)
                ldsm4(a[mi], aA + (uint32_t)((mi * 16 * GLD + kk * 8) * 4));
            #pragma unroll
            for (int p = 0; p < 2; p++)
                ldsm4(b2[p], bA + (uint32_t)((p * 16 * GLD + kk * 8) * 4));
            #pragma unroll
            for (int mi = 0; mi < 4; mi++)
                #pragma unroll
                for (int ni = 0; ni < 4; ni++)
                    mma8(acc[mi][ni], a[mi], b2[ni >> 1] + (ni & 1) * 2);
        }
        s_cur = s_nxt;
    }

    const int h = (n0 + wn * 32) >> 6;
    #pragma unroll
    for (int ni = 0; ni < 4; ni++) {
        int gcol = n0 + wn * 32 + ni * 8 + 2 * tg;
        int d    = gcol & 63;
        float b0 = bias[gcol], b1 = bias[gcol + 1];
        #pragma unroll
        for (int mi = 0; mi < 4; mi++) {
            int r0 = m0 + wm * 64 + mi * 16 + g;
            int r1 = r0 + 8;
            int b_0 = r0 >> 11, s0 = r0 & (SS - 1);
            int b_1 = r1 >> 11, s1 = r1 & (SS - 1);
            float v00 = acc[mi][ni][0] + b0, v01 = acc[mi][ni][1] + b1;
            float v10 = acc[mi][ni][2] + b0, v11 = acc[mi][ni][3] + b1;
            if (sel == 0) {          // Q: pre-scale by log2(e)/8
                uint32_t* p0 = g_q + (((size_t)(b_0 * HH + h) * SS + s0) * DK) + d;
                uint32_t* p1 = g_q + (((size_t)(b_1 * HH + h) * SS + s1) * DK) + d;
                *(uint2*)p0 = make_uint2(f2tf32(v00 * QSCALE), f2tf32(v01 * QSCALE));
                *(uint2*)p1 = make_uint2(f2tf32(v10 * QSCALE), f2tf32(v11 * QSCALE));
            } else if (sel == 1) {
                uint32_t* p0 = g_k + (((size_t)(b_0 * HH + h) * SS + s0) * DK) + d;
                uint32_t* p1 = g_k + (((size_t)(b_1 * HH + h) * SS + s1) * DK) + d;
                *(uint2*)p0 = make_uint2(f2tf32(v00), f2tf32(v01));
                *(uint2*)p1 = make_uint2(f2tf32(v10), f2tf32(v11));
            } else {
                int s0p = (s0 & ~7) | ((s0 >> 1) & 3) | ((s0 & 1) << 2);
                int s1p = (s1 & ~7) | ((s1 >> 1) & 3) | ((s1 & 1) << 2);
                uint32_t* vb = g_v + ((size_t)(b_0 * HH + h) * DK + d) * SS;
                vb[s0p]      = f2tf32(v00);
                vb[SS + s0p] = f2tf32(v01);
                uint32_t* vb1 = g_v + ((size_t)(b_1 * HH + h) * DK + d) * SS;
                vb1[s1p]      = f2tf32(v10);
                vb1[SS + s1p] = f2tf32(v11);
            }
        }
    }
}

// ===========================================================================
// Flash attention v8: 256 threads, 8 warps x 16q; phase-mixed softmax+PV
// (per n-tile: ex2 -> mask-truncate -> PV MMAs), rowsum from truncated P.
// 3-stage cp.async ring, one barrier per tile.
// ===========================================================================
#define KLD   68
#define BUFW  (64 * KLD)
#define A_STAGE (2 * BUFW * 4)              // 34816 B
#define ATTN_SMEM (3 * A_STAGE)             // 104448 B

__global__ __launch_bounds__(256, 2) void attn_tc(float* __restrict__ out)
{
    extern __shared__ uint32_t sm[];
    const uint32_t sb = smem_u32(sm);

    const int t    = threadIdx.x;
    const int wid  = t >> 5;
    const int lane = t & 31;
    const int g    = lane >> 2;
    const int tg   = lane & 3;
    const int bh   = blockIdx.y;
    const int q0   = blockIdx.x * 128;

    const uint32_t* Qp = g_q + ((size_t)bh * SS + q0) * DK;
    const uint32_t* Kp = g_k + (size_t)bh * SS * DK;
    const uint32_t* Vp = g_v + (size_t)bh * DK * SS;

    // ---- stage Q (128 rows x 64 words) into stage-0 region ----
    {
        const int qrow = t >> 1;
        const int qcol = (t & 1) * 32;
        #pragma unroll
        for (int c = 0; c < 8; c++)
            cp16(sb + (uint32_t)((qrow * KLD + qcol + c * 4) * 4),
                 Qp + (size_t)qrow * DK + qcol + c * 4);
    }
    CP_COMMIT();
    CP_WAIT0();
    __syncthreads();

    const int lane15  = lane & 15;
    const int lane7   = lane & 7;
    const int laneHi  = (lane >> 4) & 1;
    const int laneMid = (lane >> 3) & 1;
    const int arow0   = wid * 16;          // 16-q band per warp

    // ---- extract Q fragments (one m16 tile per warp) ----
    uint32_t qf[8][4];
    {
        uint32_t qa = sb +
            (uint32_t)(((arow0 + lane15) * KLD + laneHi * 4) * 4);
        #pragma unroll
        for (int k0 = 0; k0 < 8; k0++)
            ldsm4(qf[k0], qa + (uint32_t)(k0 * 32));
    }
    __syncthreads();   // Q frags read before tile0 overwrites stage 0

    // loader: thread t -> key row t>>2, quarter (t&3)*16 words (4 cp16 each)
    const int lrow = t >> 2;
    const int lcol = (t & 3) * 16;
    const uint32_t kld = (uint32_t)((lrow * KLD + lcol) * 4);

    const uint32_t kaL = (uint32_t)(((laneHi * 8 + lane7) * KLD + laneMid * 4) * 4);
    const uint32_t vaL = kaL + (uint32_t)(BUFW * 4);

    float cacc[8][4] = {};
    float rs[2] = {0.f, 0.f};

    // issue tile 0 -> stage 0
    {
        const uint32_t* ks = Kp + (size_t)lrow * DK + lcol;
        const uint32_t* vs = Vp + (size_t)lrow * SS + lcol;
        #pragma unroll
        for (int c = 0; c < 4; c++) {
            cp16(sb + kld + (uint32_t)(c * 16), ks + c * 4);
            cp16(sb + (uint32_t)(BUFW * 4) + kld + (uint32_t)(c * 16), vs + c * 4);
        }
        CP_COMMIT();
    }

    int s_cur = 0;
    for (int kt = 0; kt < SS / 64; kt++) {
        int s_nxt = (s_cur == 2) ? 0 : s_cur + 1;
        if (kt + 1 < SS / 64) {
            const uint32_t bs = sb + (uint32_t)(s_nxt * A_STAGE);
            const uint32_t* ks = Kp + (size_t)((kt + 1) * 64 + lrow) * DK + lcol;
            const uint32_t* vs = Vp + (size_t)lrow * SS + (kt + 1) * 64 + lcol;
            #pragma unroll
            for (int c = 0; c < 4; c++) {
                cp16(bs + kld + (uint32_t)(c * 16), ks + c * 4);
                cp16(bs + (uint32_t)(BUFW * 4) + kld + (uint32_t)(c * 16), vs + c * 4);
            }
            CP_COMMIT();
            CP_WAIT1();
        } else {
            CP_WAIT0();
        }
        __syncthreads();   // the only barrier per tile

        const uint32_t stb = sb + (uint32_t)(s_cur * A_STAGE);
        const uint32_t kac = stb + kaL;
        const uint32_t vac = stb + vaL;

        // ---- S = (log2e/8)(Q K^T) : 16q x 64k per warp ----
        float sc[8][4] = {};
        #pragma unroll
        for (int k0 = 0; k0 < 8; k0++) {
            #pragma unroll
            for (int ni = 0; ni < 8; ni += 2) {
                uint32_t b[4];
                ldsm4(b, kac + (uint32_t)((ni * 8 * KLD + k0 * 8) * 4));
                mma8(sc[ni],     qf[k0], b);
                mma8(sc[ni + 1], qf[k0], b + 2);
            }
        }

        // ---- phase-mixed: per n-tile, P = 2^S (ex2), truncate to tf32 by
        //      bit-mask, rowsum from TRUNCATED values, then PV MMAs ----
        #pragma unroll
        for (int ni = 0; ni < 8; ni++) {
            float e0 = ex2f(sc[ni][0]);
            float e1 = ex2f(sc[ni][1]);
            float e2 = ex2f(sc[ni][2]);
            float e3 = ex2f(sc[ni][3]);
            uint32_t pa[4];
            pa[0] = __float_as_uint(e0) & 0xFFFFE000u;
            pa[1] = __float_as_uint(e2) & 0xFFFFE000u;
            pa[2] = __float_as_uint(e1) & 0xFFFFE000u;
            pa[3] = __float_as_uint(e3) & 0xFFFFE000u;
            rs[0] += __uint_as_float(pa[0]) + __uint_as_float(pa[2]);
            rs[1] += __uint_as_float(pa[1]) + __uint_as_float(pa[3]);
            #pragma unroll
            for (int dt = 0; dt < 8; dt += 2) {
                uint32_t b[4];
                ldsm4(b, vac + (uint32_t)((dt * 8 * KLD + ni * 8) * 4));
                mma8(cacc[dt],     pa, b);
                mma8(cacc[dt + 1], pa, b + 2);
            }
        }
        s_cur = s_nxt;
    }

    // ---- rowsum quad-reduce, normalize, store ----
    rs[0] += __shfl_xor_sync(0xFFFFFFFF, rs[0], 1);
    rs[0] += __shfl_xor_sync(0xFFFFFFFF, rs[0], 2);
    rs[1] += __shfl_xor_sync(0xFFFFFFFF, rs[1], 1);
    rs[1] += __shfl_xor_sync(0xFFFFFFFF, rs[1], 2);
    const float inv0 = 1.f / (rs[0] + 1e-8f);
    const float inv1 = 1.f / (rs[1] + 1e-8f);

    const int b_ = bh / HH;
    const int h  = bh % HH;
    const int r0 = q0 + arow0 + g;
    const int r1 = r0 + 8;
    float* o0 = out + (size_t)(b_ * SS + r0) * DM + h * DK;
    float* o1 = out + (size_t)(b_ * SS + r1) * DM + h * DK;
    #pragma unroll
    for (int ni = 0; ni < 8; ni++) {
        int d = ni * 8 + 2 * tg;
        *(float2*)(o0 + d) = make_float2(cacc[ni][0] * inv0, cacc[ni][1] * inv0);
        *(float2*)(o1 + d) = make_float2(cacc[ni][2] * inv1, cacc[ni][3] * inv1);
    }
}

// ===========================================================================
extern "C" void kernel_launch(void* const* d_in, const int* in_sizes, int n_in,
                              void* d_out, int out_size)
{
    const float* x  = (const float*)d_in[0];
    const float* Wq = (const float*)d_in[1];
    const float* bq = (const float*)d_in[2];
    const float* Wk = (const float*)d_in[3];
    const float* bk = (const float*)d_in[4];
    const float* Wv = (const float*)d_in[5];
    const float* bv = (const float*)d_in[6];
    float* out = (float*)d_out;

    cudaFuncSetAttribute(qkv_gemm_tc,
                         cudaFuncAttributeMaxDynamicSharedMemorySize, GEMM_SMEM);
    cudaFuncSetAttribute(attn_tc,
                         cudaFuncAttributeMaxDynamicSharedMemorySize, ATTN_SMEM);

    xconv<<<MTOT, 256>>>(x);
    wtrans<<<dim3(32, 32, 3), 256>>>(Wq, Wk, Wv);

    dim3 ggrid(DM / 128, MTOT / 128, 3);   // (8, 32, 3)
    qkv_gemm_tc<<<ggrid, 256, GEMM_SMEM>>>(bq, bk, bv);

    dim3 agrid(SS / 128, BB * HH);         // (16, 32)
    attn_tc<<<agrid, 256, ATTN_SMEM>>>(out);
}